// round 6
// baseline (speedup 1.0000x reference)
#include <cuda_runtime.h>
#include <cuda_bf16.h>
#include <mma.h>
#include <math.h>
#include <stdint.h>

using namespace nvcuda;

#define NFEAT 128
#define HID   64
#define NCLS  40
#define MAXN  100000
#define MAXE  600000
#define SCAN_CHUNK 4096

// ---------------- scratch ----------------
__device__ float g_t1[(size_t)MAXN * 128];   // [x@W1l | x@W1r]
__device__ float g_h [(size_t)MAXN * 64];    // hidden
__device__ float g_t2[(size_t)MAXN * 80];    // [h@W2l | h@W2r]
__device__ int   g_deg[MAXN];
__device__ int   g_cur[MAXN];
__device__ int   g_rowptr[MAXN + 1];
__device__ int   g_adj[MAXE];
__device__ int   g_bsum[32];
__device__ int   g_is64;

// ---------------- f32x2 packed math (sm_103a) ----------------
#define PACK2(d, lo, hi) asm("mov.b64 %0, {%1,%2};" : "=l"(d) : "f"(lo), "f"(hi))
#define UNPACK2(lo, hi, s) asm("mov.b64 {%0,%1}, %2;" : "=f"(lo), "=f"(hi) : "l"(s))
#define FMA2(d, a, b, c) asm("fma.rn.f32x2 %0, %1, %2, %3;" : "=l"(d) : "l"(a), "l"(b), "l"(c))

// ---------------- dtype detect ----------------
__global__ void k_detect(const void* __restrict__ ei, int E, int N) {
    __shared__ int bad;
    if (threadIdx.x == 0) bad = 0;
    __syncthreads();
    const long long* p = (const long long*)ei;
    int samples = (E < 512) ? E : 512;
    for (int i = threadIdx.x; i < samples; i += blockDim.x) {
        long long v = p[i];
        if (v < 0 || v >= (long long)N) atomicExch(&bad, 1);
    }
    __syncthreads();
    if (threadIdx.x == 0) g_is64 = bad ? 0 : 1;
}

__device__ __forceinline__ int load_idx(const void* ei, int pos) {
    if (g_is64) return (int)((const long long*)ei)[pos];
    return ((const int*)ei)[pos];
}

// g_deg is zero here (module load / re-zeroed by k_scan_part every call)
__global__ void k_hist(const void* __restrict__ ei, int E, int N) {
    int e = blockIdx.x * blockDim.x + threadIdx.x;
    if (e < E) {
        int dst = load_idx(ei, E + e);
        dst = min(max(dst, 0), N - 1);
        atomicAdd(&g_deg[dst], 1);
    }
}

// per-block local scan; also resets g_deg for the next call
__global__ void k_scan_part(int n) {
    const int tid = threadIdx.x, lane = tid & 31, wid = tid >> 5;
    __shared__ int wsum[32];
    int idx = blockIdx.x * SCAN_CHUNK + tid * 4;
    int v0 = 0, v1 = 0, v2 = 0, v3 = 0;
    if (idx + 0 < n) { v0 = g_deg[idx + 0]; g_deg[idx + 0] = 0; }
    if (idx + 1 < n) { v1 = g_deg[idx + 1]; g_deg[idx + 1] = 0; }
    if (idx + 2 < n) { v2 = g_deg[idx + 2]; g_deg[idx + 2] = 0; }
    if (idx + 3 < n) { v3 = g_deg[idx + 3]; g_deg[idx + 3] = 0; }
    int s = v0 + v1 + v2 + v3;
    int sc = s;
    #pragma unroll
    for (int d = 1; d < 32; d <<= 1) {
        int t = __shfl_up_sync(0xffffffffu, sc, d);
        if (lane >= d) sc += t;
    }
    if (lane == 31) wsum[wid] = sc;
    __syncthreads();
    if (wid == 0) {
        int ws = wsum[lane];
        #pragma unroll
        for (int d = 1; d < 32; d <<= 1) {
            int t = __shfl_up_sync(0xffffffffu, ws, d);
            if (lane >= d) ws += t;
        }
        wsum[lane] = ws;
    }
    __syncthreads();
    int warp_excl = (wid == 0) ? 0 : wsum[wid - 1];
    int excl = warp_excl + (sc - s);
    int p0 = excl + v0, p1 = p0 + v1, p2 = p1 + v2, p3 = p2 + v3;
    if (idx + 0 < n) g_rowptr[idx + 1] = p0;
    if (idx + 1 < n) g_rowptr[idx + 2] = p1;
    if (idx + 2 < n) g_rowptr[idx + 3] = p2;
    if (idx + 3 < n) g_rowptr[idx + 4] = p3;
    if (tid == 1023) g_bsum[blockIdx.x] = warp_excl + sc;
}

__global__ void k_scan_add(int n, int nb) {
    __shared__ int s_off;
    if (threadIdx.x < 32) {
        int lane = threadIdx.x;
        int v = (lane < nb) ? g_bsum[lane] : 0;
        int sc = v;
        #pragma unroll
        for (int d = 1; d < 32; d <<= 1) {
            int t = __shfl_up_sync(0xffffffffu, sc, d);
            if (lane >= d) sc += t;
        }
        if (lane == (int)blockIdx.x) s_off = sc - v;
    }
    __syncthreads();
    int off = s_off;
    int idx = blockIdx.x * SCAN_CHUNK + threadIdx.x * 4;
    if (blockIdx.x == 0 && threadIdx.x == 0) g_rowptr[0] = 0;
    if (blockIdx.x > 0) {
        #pragma unroll
        for (int i = 0; i < 4; i++)
            if (idx + i < n) g_rowptr[idx + i + 1] += off;
    }
}

// g_cur is zero here (module load / reset by final k_finish)
__global__ void k_fill(const void* __restrict__ ei, int E, int N) {
    int e = blockIdx.x * blockDim.x + threadIdx.x;
    if (e < E) {
        int dst = load_idx(ei, E + e);
        int src = load_idx(ei, e);
        dst = min(max(dst, 0), N - 1);
        src = min(max(src, 0), N - 1);
        int pos = g_rowptr[dst] + atomicAdd(&g_cur[dst], 1);
        if (pos < E) g_adj[pos] = src;
    }
}

// ---------------- GEMM1 via WMMA bf16 split: T1 = X @ [W1l|W1r] ----------------
// 128x128 tile per block, 8 warps, each warp 32x64 (2x4 m16n16k16 frags).
// 3 passes: Ahi*Whi + Ahi*Wlo + Alo*Whi (fp32 accum). smem 128KB.
#define GEMM1_SMEM (4 * 128 * 128 * 2)

__global__ void __launch_bounds__(256)
k_gemm1_wmma(const float* __restrict__ X, const float* __restrict__ W1l,
             const float* __restrict__ W1r, float* __restrict__ T, int n) {
    extern __shared__ char smraw[];
    __nv_bfloat16* Ahi = (__nv_bfloat16*)smraw;          // [128][128]
    __nv_bfloat16* Alo = Ahi + 128 * 128;
    __nv_bfloat16* Whi = Alo + 128 * 128;
    __nv_bfloat16* Wlo = Whi + 128 * 128;
    const int tid = threadIdx.x, wid = tid >> 5;
    const int row0 = blockIdx.x * 128;

    // load + split X tile (128 rows x 128 cols)
    #pragma unroll 4
    for (int it = 0; it < 16; it++) {
        int p = it * 256 + tid;           // 4096 float4 slots
        int r = p >> 5, cq = p & 31;
        float4 v = make_float4(0.f, 0.f, 0.f, 0.f);
        if (row0 + r < n) v = ((const float4*)(X + (size_t)(row0 + r) * 128))[cq];
        const float vs[4] = {v.x, v.y, v.z, v.w};
        #pragma unroll
        for (int j = 0; j < 4; j++) {
            __nv_bfloat16 h = __float2bfloat16(vs[j]);
            Ahi[r * 128 + cq * 4 + j] = h;
            Alo[r * 128 + cq * 4 + j] = __float2bfloat16(vs[j] - __bfloat162float(h));
        }
    }
    // load + split W = [W1l | W1r]  (row k, 128 out-cols; already k-major)
    #pragma unroll 4
    for (int it = 0; it < 16; it++) {
        int p = it * 256 + tid;
        int k = p >> 5, cq = p & 31;
        const float* src = (cq < 16) ? (W1l + k * 64 + cq * 4)
                                     : (W1r + k * 64 + (cq - 16) * 4);
        float4 v = *(const float4*)src;
        const float vs[4] = {v.x, v.y, v.z, v.w};
        #pragma unroll
        for (int j = 0; j < 4; j++) {
            __nv_bfloat16 h = __float2bfloat16(vs[j]);
            Whi[k * 128 + cq * 4 + j] = h;
            Wlo[k * 128 + cq * 4 + j] = __float2bfloat16(vs[j] - __bfloat162float(h));
        }
    }
    __syncthreads();

    const int m0 = (wid & 3) * 32;
    const int n0 = (wid >> 2) * 64;

    wmma::fragment<wmma::accumulator, 16, 16, 16, float> acc[2][4];
    #pragma unroll
    for (int r = 0; r < 2; r++)
        #pragma unroll
        for (int c = 0; c < 4; c++) wmma::fill_fragment(acc[r][c], 0.f);

    const __nv_bfloat16* Ap[3] = {Ahi, Ahi, Alo};
    const __nv_bfloat16* Bp[3] = {Whi, Wlo, Whi};

    #pragma unroll
    for (int pass = 0; pass < 3; pass++) {
        const __nv_bfloat16* A = Ap[pass];
        const __nv_bfloat16* B = Bp[pass];
        #pragma unroll
        for (int k = 0; k < 128; k += 16) {
            wmma::fragment<wmma::matrix_a, 16, 16, 16, __nv_bfloat16, wmma::row_major> a[2];
            wmma::load_matrix_sync(a[0], A + (m0 + 0)  * 128 + k, 128);
            wmma::load_matrix_sync(a[1], A + (m0 + 16) * 128 + k, 128);
            wmma::fragment<wmma::matrix_b, 16, 16, 16, __nv_bfloat16, wmma::row_major> b[4];
            #pragma unroll
            for (int c = 0; c < 4; c++)
                wmma::load_matrix_sync(b[c], B + k * 128 + n0 + c * 16, 128);
            #pragma unroll
            for (int r = 0; r < 2; r++)
                #pragma unroll
                for (int c = 0; c < 4; c++)
                    wmma::mma_sync(acc[r][c], a[r], b[c], acc[r][c]);
        }
    }

    // stage through smem (reuse A region) for guarded global stores
    __syncthreads();
    float* stage = (float*)smraw;        // 128x128 floats = 64KB
    #pragma unroll
    for (int r = 0; r < 2; r++)
        #pragma unroll
        for (int c = 0; c < 4; c++)
            wmma::store_matrix_sync(stage + (m0 + r * 16) * 128 + n0 + c * 16,
                                    acc[r][c], 128, wmma::mem_row_major);
    __syncthreads();
    #pragma unroll 4
    for (int it = 0; it < 16; it++) {
        int p = it * 256 + tid;
        int r = p >> 5, cq = p & 31;
        if (row0 + r < n)
            ((float4*)(T + (size_t)(row0 + r) * 128))[cq] = ((float4*)(stage + r * 128))[cq];
    }
}

// ---------------- dual GEMM (layer 2, f32x2): T[n,80] = H[n,64] @ [W2l|W2r] ----
template <int IN, int OUTH, int TM>
__global__ void __launch_bounds__(8 * (2 * OUTH / 4))
k_gemm_dual(const float* __restrict__ X, const float* __restrict__ Wl,
            const float* __restrict__ Wr, float* __restrict__ T, int n) {
    constexpr int OUT = 2 * OUTH;
    constexpr int CQ  = OUT / 4;
    constexpr int NT  = 8 * CQ;
    extern __shared__ float sm[];
    float* Ws = sm;
    float* Xs = sm + IN * OUT;
    const int tid = threadIdx.x;

    for (int i = tid; i < IN * OUTH; i += NT) {
        int k = i / OUTH, c = i % OUTH;
        Ws[k * OUT + c]        = Wl[i];
        Ws[k * OUT + OUTH + c] = Wr[i];
    }
    const int row0 = blockIdx.x * TM;
    for (int i = tid; i < TM * (IN / 4); i += NT) {
        int r = i / (IN / 4), kq = i % (IN / 4);
        float4 v = make_float4(0.f, 0.f, 0.f, 0.f);
        if (row0 + r < n) v = *(const float4*)(X + (size_t)(row0 + r) * IN + kq * 4);
        *(float4*)(Xs + r * IN + kq * 4) = v;
    }
    __syncthreads();

    const int tx = tid % CQ;
    const int ty = tid / CQ;
    const float* xrow = Xs + ty * 8 * IN;
    const float* wcol = Ws + tx * 4;

    unsigned long long acc[4][4];
    #pragma unroll
    for (int a = 0; a < 4; a++)
        #pragma unroll
        for (int b = 0; b < 4; b++) acc[a][b] = 0ull;

    for (int k = 0; k < IN; k += 4) {
        float4 xv[8];
        #pragma unroll
        for (int r = 0; r < 8; r++)
            xv[r] = *(const float4*)(xrow + r * IN + k);
        float4 wq[4];
        #pragma unroll
        for (int i = 0; i < 4; i++)
            wq[i] = *(const float4*)(wcol + (k + i) * OUT);
        #pragma unroll
        for (int i = 0; i < 4; i++) {
            unsigned long long ap[4], wd[4];
            PACK2(ap[0], (&xv[0].x)[i], (&xv[1].x)[i]);
            PACK2(ap[1], (&xv[2].x)[i], (&xv[3].x)[i]);
            PACK2(ap[2], (&xv[4].x)[i], (&xv[5].x)[i]);
            PACK2(ap[3], (&xv[6].x)[i], (&xv[7].x)[i]);
            PACK2(wd[0], wq[i].x, wq[i].x);
            PACK2(wd[1], wq[i].y, wq[i].y);
            PACK2(wd[2], wq[i].z, wq[i].z);
            PACK2(wd[3], wq[i].w, wq[i].w);
            #pragma unroll
            for (int rp = 0; rp < 4; rp++)
                #pragma unroll
                for (int c = 0; c < 4; c++)
                    FMA2(acc[rp][c], ap[rp], wd[c], acc[rp][c]);
        }
    }

    #pragma unroll
    for (int rp = 0; rp < 4; rp++) {
        int r = row0 + ty * 8 + rp * 2;
        float lo[4], hi[4];
        #pragma unroll
        for (int c = 0; c < 4; c++) UNPACK2(lo[c], hi[c], acc[rp][c]);
        if (r < n)
            *(float4*)(T + (size_t)r * OUT + tx * 4) = make_float4(lo[0], lo[1], lo[2], lo[3]);
        if (r + 1 < n)
            *(float4*)(T + (size_t)(r + 1) * OUT + tx * 4) = make_float4(hi[0], hi[1], hi[2], hi[3]);
    }
}

// ---------------- aggregate + mean + residual + bias (+sigmoid) ----------------
template <int ROWLEN, int OUTC, bool SIG>
__global__ void k_finish(const float* __restrict__ T, const float* __restrict__ bias,
                         float* __restrict__ out, int n) {
    constexpr int Q = OUTC / 4;
    int gid = blockIdx.x * blockDim.x + threadIdx.x;
    int node = gid / Q;
    int q = gid - node * Q;
    if (node >= n) return;
    int s = g_rowptr[node], e = g_rowptr[node + 1];
    float4 acc = make_float4(0.f, 0.f, 0.f, 0.f);
    for (int p = s; p < e; p++) {
        int j = g_adj[p];
        float4 v = *(const float4*)(T + (size_t)j * ROWLEN + q * 4);
        acc.x += v.x; acc.y += v.y; acc.z += v.z; acc.w += v.w;
    }
    float inv = 1.f / fmaxf((float)(e - s), 1.f);
    float4 r = *(const float4*)(T + (size_t)node * ROWLEN + OUTC + q * 4);
    float4 b = *(const float4*)(bias + q * 4);
    float4 o;
    o.x = fmaf(acc.x, inv, r.x + b.x);
    o.y = fmaf(acc.y, inv, r.y + b.y);
    o.z = fmaf(acc.z, inv, r.z + b.z);
    o.w = fmaf(acc.w, inv, r.w + b.w);
    if (SIG) {
        o.x = 1.f / (1.f + expf(-o.x));
        o.y = 1.f / (1.f + expf(-o.y));
        o.z = 1.f / (1.f + expf(-o.z));
        o.w = 1.f / (1.f + expf(-o.w));
    }
    *(float4*)(out + (size_t)node * OUTC + q * 4) = o;
    if (!SIG && q == 0) g_cur[node] = 0;   // reset for next call (final pass only)
}

// ---------------- launch ----------------
extern "C" void kernel_launch(void* const* d_in, const int* in_sizes, int n_in,
                              void* d_out, int out_size) {
    const float* x   = (const float*)d_in[0];
    const void*  ei  = d_in[1];
    const float* W1l = (const float*)d_in[2];
    const float* b1  = (const float*)d_in[3];
    const float* W1r = (const float*)d_in[4];
    const float* W2l = (const float*)d_in[5];
    const float* b2  = (const float*)d_in[6];
    const float* W2r = (const float*)d_in[7];
    float* out = (float*)d_out;

    const int N = in_sizes[0] / NFEAT;
    const int E = in_sizes[1] / 2;
    const int NB = (N + SCAN_CHUNK - 1) / SCAN_CHUNK;

    void *t1p, *hp, *t2p;
    cudaGetSymbolAddress(&t1p, g_t1);
    cudaGetSymbolAddress(&hp,  g_h);
    cudaGetSymbolAddress(&t2p, g_t2);

    cudaFuncSetAttribute(k_gemm1_wmma, cudaFuncAttributeMaxDynamicSharedMemorySize, GEMM1_SMEM);

    // graph build
    k_detect<<<1, 256>>>(ei, E, N);
    k_hist<<<(E + 255) / 256, 256>>>(ei, E, N);
    k_scan_part<<<NB, 1024>>>(N);
    k_scan_add<<<NB, 1024>>>(N, NB);
    k_fill<<<(E + 255) / 256, 256>>>(ei, E, N);

    // layer 1: tensor-core (WMMA bf16 split) GEMM + aggregate/sigmoid
    k_gemm1_wmma<<<(N + 127) / 128, 256, GEMM1_SMEM>>>(x, W1l, W1r, (float*)t1p, N);
    int tot1 = N * (HID / 4);
    k_finish<128, 64, true><<<(tot1 + 255) / 256, 256>>>((const float*)t1p, b1, (float*)hp, N);

    // layer 2
    constexpr int SMEM2 = (64 * 80 + 64 * 64) * 4;
    k_gemm_dual<64, 40, 64><<<(N + 63) / 64, 160, SMEM2>>>((const float*)hp, W2l, W2r, (float*)t2p, N);
    int tot2 = N * (NCLS / 4);
    k_finish<80, 40, false><<<(tot2 + 255) / 256, 256>>>((const float*)t2p, b2, out, N);
}

// round 7
// speedup vs baseline: 1.3505x; 1.3505x over previous
#include <cuda_runtime.h>
#include <cuda_bf16.h>
#include <mma.h>
#include <math.h>
#include <stdint.h>

using namespace nvcuda;

#define NFEAT 128
#define HID   64
#define NCLS  40
#define MAXN  100000
#define MAXE  600000
#define SCAN_CHUNK 4096
#define PADW 136                      // padded smem row (bf16 elems), 8-elem aligned

// ---------------- scratch ----------------
__device__ float g_t1[(size_t)MAXN * 128];   // [x@W1l | x@W1r]
__device__ float g_h [(size_t)MAXN * 64];    // hidden
__device__ float g_t2[(size_t)MAXN * 80];    // [h@W2l | h@W2r]
__device__ __nv_bfloat16 g_w1hi[128 * 128];  // W1 = [W1l|W1r] split hi
__device__ __nv_bfloat16 g_w1lo[128 * 128];  //                 split lo
__device__ int   g_deg[MAXN];
__device__ int   g_cur[MAXN];
__device__ int   g_rowptr[MAXN + 1];
__device__ int   g_adj[MAXE];
__device__ int   g_bsum[32];
__device__ int   g_is64;

// ---------------- f32x2 packed math (sm_103a) ----------------
#define PACK2(d, lo, hi) asm("mov.b64 %0, {%1,%2};" : "=l"(d) : "f"(lo), "f"(hi))
#define UNPACK2(lo, hi, s) asm("mov.b64 {%0,%1}, %2;" : "=f"(lo), "=f"(hi) : "l"(s))
#define FMA2(d, a, b, c) asm("fma.rn.f32x2 %0, %1, %2, %3;" : "=l"(d) : "l"(a), "l"(b), "l"(c))

// ---------------- dtype detect ----------------
__global__ void k_detect(const void* __restrict__ ei, int E, int N) {
    __shared__ int bad;
    if (threadIdx.x == 0) bad = 0;
    __syncthreads();
    const long long* p = (const long long*)ei;
    int samples = (E < 512) ? E : 512;
    for (int i = threadIdx.x; i < samples; i += blockDim.x) {
        long long v = p[i];
        if (v < 0 || v >= (long long)N) atomicExch(&bad, 1);
    }
    __syncthreads();
    if (threadIdx.x == 0) g_is64 = bad ? 0 : 1;
}

__device__ __forceinline__ int load_idx(const void* ei, int pos) {
    if (g_is64) return (int)((const long long*)ei)[pos];
    return ((const int*)ei)[pos];
}

// ---------------- W1 split (once per launch): [W1l|W1r] -> bf16 hi/lo ----------
__global__ void k_wsplit(const float* __restrict__ W1l, const float* __restrict__ W1r) {
    int p = blockIdx.x * blockDim.x + threadIdx.x;    // 4096 float4 slots
    int k = p >> 5, cq = p & 31;
    const float* src = (cq < 16) ? (W1l + k * 64 + cq * 4)
                                 : (W1r + k * 64 + (cq - 16) * 4);
    float4 v = *(const float4*)src;
    const float vs[4] = {v.x, v.y, v.z, v.w};
    #pragma unroll
    for (int j = 0; j < 4; j++) {
        __nv_bfloat16 h = __float2bfloat16(vs[j]);
        g_w1hi[k * 128 + cq * 4 + j] = h;
        g_w1lo[k * 128 + cq * 4 + j] = __float2bfloat16(vs[j] - __bfloat162float(h));
    }
}

// g_deg is zero here (module load / re-zeroed by k_scan_part every call)
__global__ void k_hist(const void* __restrict__ ei, int E, int N) {
    int e = blockIdx.x * blockDim.x + threadIdx.x;
    if (e < E) {
        int dst = load_idx(ei, E + e);
        dst = min(max(dst, 0), N - 1);
        atomicAdd(&g_deg[dst], 1);
    }
}

// per-block local scan; also resets g_deg for the next call
__global__ void k_scan_part(int n) {
    const int tid = threadIdx.x, lane = tid & 31, wid = tid >> 5;
    __shared__ int wsum[32];
    int idx = blockIdx.x * SCAN_CHUNK + tid * 4;
    int v0 = 0, v1 = 0, v2 = 0, v3 = 0;
    if (idx + 0 < n) { v0 = g_deg[idx + 0]; g_deg[idx + 0] = 0; }
    if (idx + 1 < n) { v1 = g_deg[idx + 1]; g_deg[idx + 1] = 0; }
    if (idx + 2 < n) { v2 = g_deg[idx + 2]; g_deg[idx + 2] = 0; }
    if (idx + 3 < n) { v3 = g_deg[idx + 3]; g_deg[idx + 3] = 0; }
    int s = v0 + v1 + v2 + v3;
    int sc = s;
    #pragma unroll
    for (int d = 1; d < 32; d <<= 1) {
        int t = __shfl_up_sync(0xffffffffu, sc, d);
        if (lane >= d) sc += t;
    }
    if (lane == 31) wsum[wid] = sc;
    __syncthreads();
    if (wid == 0) {
        int ws = wsum[lane];
        #pragma unroll
        for (int d = 1; d < 32; d <<= 1) {
            int t = __shfl_up_sync(0xffffffffu, ws, d);
            if (lane >= d) ws += t;
        }
        wsum[lane] = ws;
    }
    __syncthreads();
    int warp_excl = (wid == 0) ? 0 : wsum[wid - 1];
    int excl = warp_excl + (sc - s);
    int p0 = excl + v0, p1 = p0 + v1, p2 = p1 + v2, p3 = p2 + v3;
    if (idx + 0 < n) g_rowptr[idx + 1] = p0;
    if (idx + 1 < n) g_rowptr[idx + 2] = p1;
    if (idx + 2 < n) g_rowptr[idx + 3] = p2;
    if (idx + 3 < n) g_rowptr[idx + 4] = p3;
    if (tid == 1023) g_bsum[blockIdx.x] = warp_excl + sc;
}

__global__ void k_scan_add(int n, int nb) {
    __shared__ int s_off;
    if (threadIdx.x < 32) {
        int lane = threadIdx.x;
        int v = (lane < nb) ? g_bsum[lane] : 0;
        int sc = v;
        #pragma unroll
        for (int d = 1; d < 32; d <<= 1) {
            int t = __shfl_up_sync(0xffffffffu, sc, d);
            if (lane >= d) sc += t;
        }
        if (lane == (int)blockIdx.x) s_off = sc - v;
    }
    __syncthreads();
    int off = s_off;
    int idx = blockIdx.x * SCAN_CHUNK + threadIdx.x * 4;
    if (blockIdx.x == 0 && threadIdx.x == 0) g_rowptr[0] = 0;
    if (blockIdx.x > 0) {
        #pragma unroll
        for (int i = 0; i < 4; i++)
            if (idx + i < n) g_rowptr[idx + i + 1] += off;
    }
}

// g_cur is zero here (module load / reset by final k_finish)
__global__ void k_fill(const void* __restrict__ ei, int E, int N) {
    int e = blockIdx.x * blockDim.x + threadIdx.x;
    if (e < E) {
        int dst = load_idx(ei, E + e);
        int src = load_idx(ei, e);
        dst = min(max(dst, 0), N - 1);
        src = min(max(src, 0), N - 1);
        int pos = g_rowptr[dst] + atomicAdd(&g_cur[dst], 1);
        if (pos < E) g_adj[pos] = src;
    }
}

// ---------------- GEMM1 via WMMA bf16 split (v2): T1 = X @ [W1l|W1r] ----------
// 64-row tile / block, 256 threads (8 warps = 2m x 4n of 32x32 warp tiles).
// smem padded rows (PADW=136) -> conflict-free LDSM; W pre-split in global.
// 3 passes: Ahi*Whi + Ahi*Wlo + Alo*Whi, fp32 accum.  smem = 102KB -> 2 CTA/SM.
#define GEMM1_SMEM ((2 * 128 + 2 * 64) * PADW * 2)

__global__ void __launch_bounds__(256, 2)
k_gemm1_wmma(const float* __restrict__ X, float* __restrict__ T, int n) {
    extern __shared__ char smraw[];
    __nv_bfloat16* Whi = (__nv_bfloat16*)smraw;          // [128][PADW]
    __nv_bfloat16* Wlo = Whi + 128 * PADW;
    __nv_bfloat16* Ahi = Wlo + 128 * PADW;               // [64][PADW]
    __nv_bfloat16* Alo = Ahi + 64 * PADW;
    const int tid = threadIdx.x, wid = tid >> 5;
    const int row0 = blockIdx.x * 64;

    // copy pre-split W (bf16) -> padded smem; 2048 uint4 per matrix
    #pragma unroll
    for (int it = 0; it < 8; it++) {
        int p = it * 256 + tid;
        int k = p >> 4, c = p & 15;                       // 16 uint4 chunks per row
        *(uint4*)(Whi + k * PADW + c * 8) = ((const uint4*)g_w1hi)[p];
        *(uint4*)(Wlo + k * PADW + c * 8) = ((const uint4*)g_w1lo)[p];
    }
    // load + split A tile (64 rows x 128 cols)
    #pragma unroll
    for (int it = 0; it < 8; it++) {
        int p = it * 256 + tid;                           // 2048 float4 slots
        int r = p >> 5, cq = p & 31;
        float4 v = make_float4(0.f, 0.f, 0.f, 0.f);
        if (row0 + r < n) v = ((const float4*)(X + (size_t)(row0 + r) * 128))[cq];
        uint32_t h01, h23;
        asm("cvt.rn.bf16x2.f32 %0, %1, %2;" : "=r"(h01) : "f"(v.y), "f"(v.x));
        asm("cvt.rn.bf16x2.f32 %0, %1, %2;" : "=r"(h23) : "f"(v.w), "f"(v.z));
        float l0 = v.x - __uint_as_float(h01 << 16);
        float l1 = v.y - __uint_as_float(h01 & 0xffff0000u);
        float l2 = v.z - __uint_as_float(h23 << 16);
        float l3 = v.w - __uint_as_float(h23 & 0xffff0000u);
        uint32_t lo01, lo23;
        asm("cvt.rn.bf16x2.f32 %0, %1, %2;" : "=r"(lo01) : "f"(l1), "f"(l0));
        asm("cvt.rn.bf16x2.f32 %0, %1, %2;" : "=r"(lo23) : "f"(l3), "f"(l2));
        uint32_t* ah = (uint32_t*)(Ahi + r * PADW + cq * 4);
        uint32_t* al = (uint32_t*)(Alo + r * PADW + cq * 4);
        ah[0] = h01;  ah[1] = h23;
        al[0] = lo01; al[1] = lo23;
    }
    __syncthreads();

    const int m0 = (wid & 1) * 32;
    const int n0 = (wid >> 1) * 32;

    wmma::fragment<wmma::accumulator, 16, 16, 16, float> acc[2][2];
    #pragma unroll
    for (int r = 0; r < 2; r++)
        #pragma unroll
        for (int c = 0; c < 2; c++) wmma::fill_fragment(acc[r][c], 0.f);

    const __nv_bfloat16* Ap[3] = {Ahi, Ahi, Alo};
    const __nv_bfloat16* Bp[3] = {Whi, Wlo, Whi};

    #pragma unroll
    for (int pass = 0; pass < 3; pass++) {
        const __nv_bfloat16* A = Ap[pass];
        const __nv_bfloat16* B = Bp[pass];
        #pragma unroll
        for (int k = 0; k < 128; k += 16) {
            wmma::fragment<wmma::matrix_a, 16, 16, 16, __nv_bfloat16, wmma::row_major> a[2];
            wmma::load_matrix_sync(a[0], A + (m0 + 0)  * PADW + k, PADW);
            wmma::load_matrix_sync(a[1], A + (m0 + 16) * PADW + k, PADW);
            wmma::fragment<wmma::matrix_b, 16, 16, 16, __nv_bfloat16, wmma::row_major> b[2];
            wmma::load_matrix_sync(b[0], B + k * PADW + n0,      PADW);
            wmma::load_matrix_sync(b[1], B + k * PADW + n0 + 16, PADW);
            #pragma unroll
            for (int r = 0; r < 2; r++)
                #pragma unroll
                for (int c = 0; c < 2; c++)
                    wmma::mma_sync(acc[r][c], a[r], b[c], acc[r][c]);
        }
    }

    // stage through smem (reuse W region: 32KB <= 68KB) then guarded stores
    __syncthreads();
    float* stage = (float*)smraw;        // [64][128]
    #pragma unroll
    for (int r = 0; r < 2; r++)
        #pragma unroll
        for (int c = 0; c < 2; c++)
            wmma::store_matrix_sync(stage + (m0 + r * 16) * 128 + n0 + c * 16,
                                    acc[r][c], 128, wmma::mem_row_major);
    __syncthreads();
    #pragma unroll
    for (int it = 0; it < 8; it++) {
        int p = it * 256 + tid;
        int r = p >> 5, cq = p & 31;
        if (row0 + r < n)
            ((float4*)(T + (size_t)(row0 + r) * 128))[cq] = ((float4*)(stage + r * 128))[cq];
    }
}

// ---------------- dual GEMM (layer 2, f32x2): T[n,80] = H[n,64] @ [W2l|W2r] ----
template <int IN, int OUTH, int TM>
__global__ void __launch_bounds__(8 * (2 * OUTH / 4))
k_gemm_dual(const float* __restrict__ X, const float* __restrict__ Wl,
            const float* __restrict__ Wr, float* __restrict__ T, int n) {
    constexpr int OUT = 2 * OUTH;
    constexpr int CQ  = OUT / 4;
    constexpr int NT  = 8 * CQ;
    extern __shared__ float sm[];
    float* Ws = sm;
    float* Xs = sm + IN * OUT;
    const int tid = threadIdx.x;

    for (int i = tid; i < IN * OUTH; i += NT) {
        int k = i / OUTH, c = i % OUTH;
        Ws[k * OUT + c]        = Wl[i];
        Ws[k * OUT + OUTH + c] = Wr[i];
    }
    const int row0 = blockIdx.x * TM;
    for (int i = tid; i < TM * (IN / 4); i += NT) {
        int r = i / (IN / 4), kq = i % (IN / 4);
        float4 v = make_float4(0.f, 0.f, 0.f, 0.f);
        if (row0 + r < n) v = *(const float4*)(X + (size_t)(row0 + r) * IN + kq * 4);
        *(float4*)(Xs + r * IN + kq * 4) = v;
    }
    __syncthreads();

    const int tx = tid % CQ;
    const int ty = tid / CQ;
    const float* xrow = Xs + ty * 8 * IN;
    const float* wcol = Ws + tx * 4;

    unsigned long long acc[4][4];
    #pragma unroll
    for (int a = 0; a < 4; a++)
        #pragma unroll
        for (int b = 0; b < 4; b++) acc[a][b] = 0ull;

    for (int k = 0; k < IN; k += 4) {
        float4 xv[8];
        #pragma unroll
        for (int r = 0; r < 8; r++)
            xv[r] = *(const float4*)(xrow + r * IN + k);
        float4 wq[4];
        #pragma unroll
        for (int i = 0; i < 4; i++)
            wq[i] = *(const float4*)(wcol + (k + i) * OUT);
        #pragma unroll
        for (int i = 0; i < 4; i++) {
            unsigned long long ap[4], wd[4];
            PACK2(ap[0], (&xv[0].x)[i], (&xv[1].x)[i]);
            PACK2(ap[1], (&xv[2].x)[i], (&xv[3].x)[i]);
            PACK2(ap[2], (&xv[4].x)[i], (&xv[5].x)[i]);
            PACK2(ap[3], (&xv[6].x)[i], (&xv[7].x)[i]);
            PACK2(wd[0], wq[i].x, wq[i].x);
            PACK2(wd[1], wq[i].y, wq[i].y);
            PACK2(wd[2], wq[i].z, wq[i].z);
            PACK2(wd[3], wq[i].w, wq[i].w);
            #pragma unroll
            for (int rp = 0; rp < 4; rp++)
                #pragma unroll
                for (int c = 0; c < 4; c++)
                    FMA2(acc[rp][c], ap[rp], wd[c], acc[rp][c]);
        }
    }

    #pragma unroll
    for (int rp = 0; rp < 4; rp++) {
        int r = row0 + ty * 8 + rp * 2;
        float lo[4], hi[4];
        #pragma unroll
        for (int c = 0; c < 4; c++) UNPACK2(lo[c], hi[c], acc[rp][c]);
        if (r < n)
            *(float4*)(T + (size_t)r * OUT + tx * 4) = make_float4(lo[0], lo[1], lo[2], lo[3]);
        if (r + 1 < n)
            *(float4*)(T + (size_t)(r + 1) * OUT + tx * 4) = make_float4(hi[0], hi[1], hi[2], hi[3]);
    }
}

// ---------------- aggregate + mean + residual + bias (+sigmoid) ----------------
template <int ROWLEN, int OUTC, bool SIG>
__global__ void k_finish(const float* __restrict__ T, const float* __restrict__ bias,
                         float* __restrict__ out, int n) {
    constexpr int Q = OUTC / 4;
    int gid = blockIdx.x * blockDim.x + threadIdx.x;
    int node = gid / Q;
    int q = gid - node * Q;
    if (node >= n) return;
    int s = g_rowptr[node], e = g_rowptr[node + 1];
    float4 acc = make_float4(0.f, 0.f, 0.f, 0.f);
    for (int p = s; p < e; p++) {
        int j = g_adj[p];
        float4 v = *(const float4*)(T + (size_t)j * ROWLEN + q * 4);
        acc.x += v.x; acc.y += v.y; acc.z += v.z; acc.w += v.w;
    }
    float inv = 1.f / fmaxf((float)(e - s), 1.f);
    float4 r = *(const float4*)(T + (size_t)node * ROWLEN + OUTC + q * 4);
    float4 b = *(const float4*)(bias + q * 4);
    float4 o;
    o.x = fmaf(acc.x, inv, r.x + b.x);
    o.y = fmaf(acc.y, inv, r.y + b.y);
    o.z = fmaf(acc.z, inv, r.z + b.z);
    o.w = fmaf(acc.w, inv, r.w + b.w);
    if (SIG) {
        o.x = 1.f / (1.f + expf(-o.x));
        o.y = 1.f / (1.f + expf(-o.y));
        o.z = 1.f / (1.f + expf(-o.z));
        o.w = 1.f / (1.f + expf(-o.w));
    }
    *(float4*)(out + (size_t)node * OUTC + q * 4) = o;
    if (!SIG && q == 0) g_cur[node] = 0;   // reset for next call (final pass only)
}

// ---------------- launch ----------------
extern "C" void kernel_launch(void* const* d_in, const int* in_sizes, int n_in,
                              void* d_out, int out_size) {
    const float* x   = (const float*)d_in[0];
    const void*  ei  = d_in[1];
    const float* W1l = (const float*)d_in[2];
    const float* b1  = (const float*)d_in[3];
    const float* W1r = (const float*)d_in[4];
    const float* W2l = (const float*)d_in[5];
    const float* b2  = (const float*)d_in[6];
    const float* W2r = (const float*)d_in[7];
    float* out = (float*)d_out;

    const int N = in_sizes[0] / NFEAT;
    const int E = in_sizes[1] / 2;
    const int NB = (N + SCAN_CHUNK - 1) / SCAN_CHUNK;

    void *t1p, *hp, *t2p;
    cudaGetSymbolAddress(&t1p, g_t1);
    cudaGetSymbolAddress(&hp,  g_h);
    cudaGetSymbolAddress(&t2p, g_t2);

    cudaFuncSetAttribute(k_gemm1_wmma, cudaFuncAttributeMaxDynamicSharedMemorySize, GEMM1_SMEM);

    // graph build + W split
    k_detect<<<1, 256>>>(ei, E, N);
    k_wsplit<<<16, 256>>>(W1l, W1r);
    k_hist<<<(E + 255) / 256, 256>>>(ei, E, N);
    k_scan_part<<<NB, 1024>>>(N);
    k_scan_add<<<NB, 1024>>>(N, NB);
    k_fill<<<(E + 255) / 256, 256>>>(ei, E, N);

    // layer 1: tensor-core (WMMA bf16 split v2) GEMM + aggregate/sigmoid
    k_gemm1_wmma<<<(N + 63) / 64, 256, GEMM1_SMEM>>>(x, (float*)t1p, N);
    int tot1 = N * (HID / 4);
    k_finish<128, 64, true><<<(tot1 + 255) / 256, 256>>>((const float*)t1p, b1, (float*)hp, N);

    // layer 2
    constexpr int SMEM2 = (64 * 80 + 64 * 64) * 4;
    k_gemm_dual<64, 40, 64><<<(N + 63) / 64, 160, SMEM2>>>((const float*)hp, W2l, W2r, (float*)t2p, N);
    int tot2 = N * (NCLS / 4);
    k_finish<80, 40, false><<<(tot2 + 255) / 256, 256>>>((const float*)t2p, b2, out, N);
}

// round 8
// speedup vs baseline: 1.3957x; 1.0334x over previous
#include <cuda_runtime.h>
#include <cuda_bf16.h>
#include <mma.h>
#include <math.h>
#include <stdint.h>

using namespace nvcuda;

#define NFEAT 128
#define HID   64
#define NCLS  40
#define MAXN  100000
#define MAXE  600000
#define SCAN_CHUNK 4096
#define PADW 136                      // padded smem row (bf16 elems)

// ---------------- scratch ----------------
__device__ float g_t1[(size_t)MAXN * 128];   // [x@W1l | x@W1r]
__device__ float g_h [(size_t)MAXN * 64];    // hidden
__device__ float g_t2[(size_t)MAXN * 80];    // [h@W2l | h@W2r]
__device__ __nv_bfloat16 g_w1hi[128 * 128];
__device__ __nv_bfloat16 g_w1lo[128 * 128];
__device__ int   g_deg[MAXN];
__device__ int   g_cur[MAXN];
__device__ int   g_rowptr[MAXN + 1];
__device__ int   g_adj[MAXE];
__device__ int   g_bsum[32];
__device__ int   g_bflag[32];
__device__ int   g_is64;

// ---------------- side stream for capture fork (created once at load) -------
static cudaStream_t g_s2;
static cudaEvent_t  g_evFork, g_evJoin;
static struct _StreamInit {
    _StreamInit() {
        cudaStreamCreateWithFlags(&g_s2, cudaStreamNonBlocking);
        cudaEventCreateWithFlags(&g_evFork, cudaEventDisableTiming);
        cudaEventCreateWithFlags(&g_evJoin, cudaEventDisableTiming);
    }
} g_streamInit;

// ---------------- f32x2 packed math (sm_103a) ----------------
#define PACK2(d, lo, hi) asm("mov.b64 %0, {%1,%2};" : "=l"(d) : "f"(lo), "f"(hi))
#define UNPACK2(lo, hi, s) asm("mov.b64 {%0,%1}, %2;" : "=f"(lo), "=f"(hi) : "l"(s))
#define FMA2(d, a, b, c) asm("fma.rn.f32x2 %0, %1, %2, %3;" : "=l"(d) : "l"(a), "l"(b), "l"(c))

// ---------------- dtype detect ----------------
__global__ void k_detect(const void* __restrict__ ei, int E, int N) {
    __shared__ int bad;
    if (threadIdx.x == 0) bad = 0;
    __syncthreads();
    const long long* p = (const long long*)ei;
    int samples = (E < 512) ? E : 512;
    for (int i = threadIdx.x; i < samples; i += blockDim.x) {
        long long v = p[i];
        if (v < 0 || v >= (long long)N) atomicExch(&bad, 1);
    }
    __syncthreads();
    if (threadIdx.x == 0) g_is64 = bad ? 0 : 1;
}

__device__ __forceinline__ int load_idx(const void* ei, int pos) {
    if (g_is64) return (int)((const long long*)ei)[pos];
    return ((const int*)ei)[pos];
}

// ---------------- W1 split: [W1l|W1r] -> bf16 hi/lo ----------
__global__ void k_wsplit(const float* __restrict__ W1l, const float* __restrict__ W1r) {
    int p = blockIdx.x * blockDim.x + threadIdx.x;    // 4096 float4 slots
    int k = p >> 5, cq = p & 31;
    const float* src = (cq < 16) ? (W1l + k * 64 + cq * 4)
                                 : (W1r + k * 64 + (cq - 16) * 4);
    float4 v = *(const float4*)src;
    const float vs[4] = {v.x, v.y, v.z, v.w};
    #pragma unroll
    for (int j = 0; j < 4; j++) {
        __nv_bfloat16 h = __float2bfloat16(vs[j]);
        g_w1hi[k * 128 + cq * 4 + j] = h;
        g_w1lo[k * 128 + cq * 4 + j] = __float2bfloat16(vs[j] - __bfloat162float(h));
    }
}

// g_deg is zero here (module load / re-zeroed by k_scan every call)
__global__ void k_hist(const void* __restrict__ ei, int E, int N) {
    int e = blockIdx.x * blockDim.x + threadIdx.x;
    if (e < E) {
        int dst = load_idx(ei, E + e);
        dst = min(max(dst, 0), N - 1);
        atomicAdd(&g_deg[dst], 1);
    }
}

// ---- single-pass scan: local scan + decoupled block-sum lookback ----
// 25 blocks always co-resident (<<148 SMs) -> spin-poll is safe.
// g_bflag zeroed at module load and reset by k_fill each call.
__global__ void k_scan(int n) {
    const int tid = threadIdx.x, lane = tid & 31, wid = tid >> 5;
    const int bid = blockIdx.x;
    __shared__ int wsum[32];
    __shared__ int s_off;
    int idx = bid * SCAN_CHUNK + tid * 4;
    int v0 = 0, v1 = 0, v2 = 0, v3 = 0;
    if (idx + 0 < n) { v0 = g_deg[idx + 0]; g_deg[idx + 0] = 0; }
    if (idx + 1 < n) { v1 = g_deg[idx + 1]; g_deg[idx + 1] = 0; }
    if (idx + 2 < n) { v2 = g_deg[idx + 2]; g_deg[idx + 2] = 0; }
    if (idx + 3 < n) { v3 = g_deg[idx + 3]; g_deg[idx + 3] = 0; }
    int s = v0 + v1 + v2 + v3;
    int sc = s;
    #pragma unroll
    for (int d = 1; d < 32; d <<= 1) {
        int t = __shfl_up_sync(0xffffffffu, sc, d);
        if (lane >= d) sc += t;
    }
    if (lane == 31) wsum[wid] = sc;
    __syncthreads();
    if (wid == 0) {
        int ws = wsum[lane];
        #pragma unroll
        for (int d = 1; d < 32; d <<= 1) {
            int t = __shfl_up_sync(0xffffffffu, ws, d);
            if (lane >= d) ws += t;
        }
        wsum[lane] = ws;
    }
    __syncthreads();
    int warp_excl = (wid == 0) ? 0 : wsum[wid - 1];
    int excl = warp_excl + (sc - s);

    // publish this block's total, then look back over predecessors
    if (tid == 1023) {
        g_bsum[bid] = warp_excl + sc;
        __threadfence();
        atomicExch(&g_bflag[bid], 1);
    }
    if (tid < 32) {
        int acc = 0;
        for (int j = lane; j < bid; j += 32) {
            while (atomicAdd(&g_bflag[j], 0) == 0) {}
            acc += atomicAdd(&g_bsum[j], 0);
        }
        #pragma unroll
        for (int d = 16; d > 0; d >>= 1)
            acc += __shfl_down_sync(0xffffffffu, acc, d);
        if (lane == 0) s_off = acc;
    }
    __syncthreads();
    int off = s_off + excl;
    int p0 = off + v0, p1 = p0 + v1, p2 = p1 + v2, p3 = p2 + v3;
    if (idx + 0 < n) g_rowptr[idx + 1] = p0;
    if (idx + 1 < n) g_rowptr[idx + 2] = p1;
    if (idx + 2 < n) g_rowptr[idx + 3] = p2;
    if (idx + 3 < n) g_rowptr[idx + 4] = p3;
    if (bid == 0 && tid == 0) g_rowptr[0] = 0;
}

// g_cur is zero here (module load / reset by final k_finish)
__global__ void k_fill(const void* __restrict__ ei, int E, int N) {
    if (blockIdx.x == 0 && threadIdx.x < 32) g_bflag[threadIdx.x] = 0;  // reset for next call
    int e = blockIdx.x * blockDim.x + threadIdx.x;
    if (e < E) {
        int dst = load_idx(ei, E + e);
        int src = load_idx(ei, e);
        dst = min(max(dst, 0), N - 1);
        src = min(max(src, 0), N - 1);
        int pos = g_rowptr[dst] + atomicAdd(&g_cur[dst], 1);
        if (pos < E) g_adj[pos] = src;
    }
}

// ---------------- GEMM1 via WMMA bf16 split (v2): T1 = X @ [W1l|W1r] ----------
#define GEMM1_SMEM ((2 * 128 + 2 * 64) * PADW * 2)

__global__ void __launch_bounds__(256, 2)
k_gemm1_wmma(const float* __restrict__ X, float* __restrict__ T, int n) {
    extern __shared__ char smraw[];
    __nv_bfloat16* Whi = (__nv_bfloat16*)smraw;          // [128][PADW]
    __nv_bfloat16* Wlo = Whi + 128 * PADW;
    __nv_bfloat16* Ahi = Wlo + 128 * PADW;               // [64][PADW]
    __nv_bfloat16* Alo = Ahi + 64 * PADW;
    const int tid = threadIdx.x, wid = tid >> 5;
    const int row0 = blockIdx.x * 64;

    #pragma unroll
    for (int it = 0; it < 8; it++) {
        int p = it * 256 + tid;
        int k = p >> 4, c = p & 15;
        *(uint4*)(Whi + k * PADW + c * 8) = ((const uint4*)g_w1hi)[p];
        *(uint4*)(Wlo + k * PADW + c * 8) = ((const uint4*)g_w1lo)[p];
    }
    #pragma unroll
    for (int it = 0; it < 8; it++) {
        int p = it * 256 + tid;
        int r = p >> 5, cq = p & 31;
        float4 v = make_float4(0.f, 0.f, 0.f, 0.f);
        if (row0 + r < n) v = ((const float4*)(X + (size_t)(row0 + r) * 128))[cq];
        uint32_t h01, h23;
        asm("cvt.rn.bf16x2.f32 %0, %1, %2;" : "=r"(h01) : "f"(v.y), "f"(v.x));
        asm("cvt.rn.bf16x2.f32 %0, %1, %2;" : "=r"(h23) : "f"(v.w), "f"(v.z));
        float l0 = v.x - __uint_as_float(h01 << 16);
        float l1 = v.y - __uint_as_float(h01 & 0xffff0000u);
        float l2 = v.z - __uint_as_float(h23 << 16);
        float l3 = v.w - __uint_as_float(h23 & 0xffff0000u);
        uint32_t lo01, lo23;
        asm("cvt.rn.bf16x2.f32 %0, %1, %2;" : "=r"(lo01) : "f"(l1), "f"(l0));
        asm("cvt.rn.bf16x2.f32 %0, %1, %2;" : "=r"(lo23) : "f"(l3), "f"(l2));
        uint32_t* ah = (uint32_t*)(Ahi + r * PADW + cq * 4);
        uint32_t* al = (uint32_t*)(Alo + r * PADW + cq * 4);
        ah[0] = h01;  ah[1] = h23;
        al[0] = lo01; al[1] = lo23;
    }
    __syncthreads();

    const int m0 = (wid & 1) * 32;
    const int n0 = (wid >> 1) * 32;

    wmma::fragment<wmma::accumulator, 16, 16, 16, float> acc[2][2];
    #pragma unroll
    for (int r = 0; r < 2; r++)
        #pragma unroll
        for (int c = 0; c < 2; c++) wmma::fill_fragment(acc[r][c], 0.f);

    const __nv_bfloat16* Ap[3] = {Ahi, Ahi, Alo};
    const __nv_bfloat16* Bp[3] = {Whi, Wlo, Whi};

    #pragma unroll
    for (int pass = 0; pass < 3; pass++) {
        const __nv_bfloat16* A = Ap[pass];
        const __nv_bfloat16* B = Bp[pass];
        #pragma unroll
        for (int k = 0; k < 128; k += 16) {
            wmma::fragment<wmma::matrix_a, 16, 16, 16, __nv_bfloat16, wmma::row_major> a[2];
            wmma::load_matrix_sync(a[0], A + (m0 + 0)  * PADW + k, PADW);
            wmma::load_matrix_sync(a[1], A + (m0 + 16) * PADW + k, PADW);
            wmma::fragment<wmma::matrix_b, 16, 16, 16, __nv_bfloat16, wmma::row_major> b[2];
            wmma::load_matrix_sync(b[0], B + k * PADW + n0,      PADW);
            wmma::load_matrix_sync(b[1], B + k * PADW + n0 + 16, PADW);
            #pragma unroll
            for (int r = 0; r < 2; r++)
                #pragma unroll
                for (int c = 0; c < 2; c++)
                    wmma::mma_sync(acc[r][c], a[r], b[c], acc[r][c]);
        }
    }

    __syncthreads();
    float* stage = (float*)smraw;        // [64][128]
    #pragma unroll
    for (int r = 0; r < 2; r++)
        #pragma unroll
        for (int c = 0; c < 2; c++)
            wmma::store_matrix_sync(stage + (m0 + r * 16) * 128 + n0 + c * 16,
                                    acc[r][c], 128, wmma::mem_row_major);
    __syncthreads();
    #pragma unroll
    for (int it = 0; it < 8; it++) {
        int p = it * 256 + tid;
        int r = p >> 5, cq = p & 31;
        if (row0 + r < n)
            ((float4*)(T + (size_t)(row0 + r) * 128))[cq] = ((float4*)(stage + r * 128))[cq];
    }
}

// ---------------- dual GEMM (layer 2, f32x2): T[n,80] = H[n,64] @ [W2l|W2r] ----
template <int IN, int OUTH, int TM>
__global__ void __launch_bounds__(8 * (2 * OUTH / 4))
k_gemm_dual(const float* __restrict__ X, const float* __restrict__ Wl,
            const float* __restrict__ Wr, float* __restrict__ T, int n) {
    constexpr int OUT = 2 * OUTH;
    constexpr int CQ  = OUT / 4;
    constexpr int NT  = 8 * CQ;
    extern __shared__ float sm[];
    float* Ws = sm;
    float* Xs = sm + IN * OUT;
    const int tid = threadIdx.x;

    for (int i = tid; i < IN * OUTH; i += NT) {
        int k = i / OUTH, c = i % OUTH;
        Ws[k * OUT + c]        = Wl[i];
        Ws[k * OUT + OUTH + c] = Wr[i];
    }
    const int row0 = blockIdx.x * TM;
    for (int i = tid; i < TM * (IN / 4); i += NT) {
        int r = i / (IN / 4), kq = i % (IN / 4);
        float4 v = make_float4(0.f, 0.f, 0.f, 0.f);
        if (row0 + r < n) v = *(const float4*)(X + (size_t)(row0 + r) * IN + kq * 4);
        *(float4*)(Xs + r * IN + kq * 4) = v;
    }
    __syncthreads();

    const int tx = tid % CQ;
    const int ty = tid / CQ;
    const float* xrow = Xs + ty * 8 * IN;
    const float* wcol = Ws + tx * 4;

    unsigned long long acc[4][4];
    #pragma unroll
    for (int a = 0; a < 4; a++)
        #pragma unroll
        for (int b = 0; b < 4; b++) acc[a][b] = 0ull;

    for (int k = 0; k < IN; k += 4) {
        float4 xv[8];
        #pragma unroll
        for (int r = 0; r < 8; r++)
            xv[r] = *(const float4*)(xrow + r * IN + k);
        float4 wq[4];
        #pragma unroll
        for (int i = 0; i < 4; i++)
            wq[i] = *(const float4*)(wcol + (k + i) * OUT);
        #pragma unroll
        for (int i = 0; i < 4; i++) {
            unsigned long long ap[4], wd[4];
            PACK2(ap[0], (&xv[0].x)[i], (&xv[1].x)[i]);
            PACK2(ap[1], (&xv[2].x)[i], (&xv[3].x)[i]);
            PACK2(ap[2], (&xv[4].x)[i], (&xv[5].x)[i]);
            PACK2(ap[3], (&xv[6].x)[i], (&xv[7].x)[i]);
            PACK2(wd[0], wq[i].x, wq[i].x);
            PACK2(wd[1], wq[i].y, wq[i].y);
            PACK2(wd[2], wq[i].z, wq[i].z);
            PACK2(wd[3], wq[i].w, wq[i].w);
            #pragma unroll
            for (int rp = 0; rp < 4; rp++)
                #pragma unroll
                for (int c = 0; c < 4; c++)
                    FMA2(acc[rp][c], ap[rp], wd[c], acc[rp][c]);
        }
    }

    #pragma unroll
    for (int rp = 0; rp < 4; rp++) {
        int r = row0 + ty * 8 + rp * 2;
        float lo[4], hi[4];
        #pragma unroll
        for (int c = 0; c < 4; c++) UNPACK2(lo[c], hi[c], acc[rp][c]);
        if (r < n)
            *(float4*)(T + (size_t)r * OUT + tx * 4) = make_float4(lo[0], lo[1], lo[2], lo[3]);
        if (r + 1 < n)
            *(float4*)(T + (size_t)(r + 1) * OUT + tx * 4) = make_float4(hi[0], hi[1], hi[2], hi[3]);
    }
}

// ---------------- aggregate + mean + residual + bias (+sigmoid) ----------------
template <int ROWLEN, int OUTC, bool SIG>
__global__ void k_finish(const float* __restrict__ T, const float* __restrict__ bias,
                         float* __restrict__ out, int n) {
    constexpr int Q = OUTC / 4;
    int gid = blockIdx.x * blockDim.x + threadIdx.x;
    int node = gid / Q;
    int q = gid - node * Q;
    if (node >= n) return;
    int s = g_rowptr[node], e = g_rowptr[node + 1];
    float4 acc = make_float4(0.f, 0.f, 0.f, 0.f);
    for (int p = s; p < e; p++) {
        int j = g_adj[p];
        float4 v = *(const float4*)(T + (size_t)j * ROWLEN + q * 4);
        acc.x += v.x; acc.y += v.y; acc.z += v.z; acc.w += v.w;
    }
    float inv = 1.f / fmaxf((float)(e - s), 1.f);
    float4 r = *(const float4*)(T + (size_t)node * ROWLEN + OUTC + q * 4);
    float4 b = *(const float4*)(bias + q * 4);
    float4 o;
    o.x = fmaf(acc.x, inv, r.x + b.x);
    o.y = fmaf(acc.y, inv, r.y + b.y);
    o.z = fmaf(acc.z, inv, r.z + b.z);
    o.w = fmaf(acc.w, inv, r.w + b.w);
    if (SIG) {
        o.x = 1.f / (1.f + expf(-o.x));
        o.y = 1.f / (1.f + expf(-o.y));
        o.z = 1.f / (1.f + expf(-o.z));
        o.w = 1.f / (1.f + expf(-o.w));
    }
    *(float4*)(out + (size_t)node * OUTC + q * 4) = o;
    if (!SIG && q == 0) g_cur[node] = 0;   // reset for next call (final pass only)
}

// ---------------- launch ----------------
extern "C" void kernel_launch(void* const* d_in, const int* in_sizes, int n_in,
                              void* d_out, int out_size) {
    const float* x   = (const float*)d_in[0];
    const void*  ei  = d_in[1];
    const float* W1l = (const float*)d_in[2];
    const float* b1  = (const float*)d_in[3];
    const float* W1r = (const float*)d_in[4];
    const float* W2l = (const float*)d_in[5];
    const float* b2  = (const float*)d_in[6];
    const float* W2r = (const float*)d_in[7];
    float* out = (float*)d_out;

    const int N = in_sizes[0] / NFEAT;
    const int E = in_sizes[1] / 2;
    const int NB = (N + SCAN_CHUNK - 1) / SCAN_CHUNK;

    void *t1p, *hp, *t2p;
    cudaGetSymbolAddress(&t1p, g_t1);
    cudaGetSymbolAddress(&hp,  g_h);
    cudaGetSymbolAddress(&t2p, g_t2);

    cudaFuncSetAttribute(k_gemm1_wmma, cudaFuncAttributeMaxDynamicSharedMemorySize, GEMM1_SMEM);

    // fork: side stream runs W-split + GEMM1 while main stream builds the graph
    cudaEventRecord(g_evFork, 0);
    cudaStreamWaitEvent(g_s2, g_evFork, 0);

    // main stream: graph build
    k_detect<<<1, 256>>>(ei, E, N);
    k_hist<<<(E + 255) / 256, 256>>>(ei, E, N);
    k_scan<<<NB, 1024>>>(N);
    k_fill<<<(E + 255) / 256, 256>>>(ei, E, N);

    // side stream: weights + layer-1 GEMM (independent of graph build)
    k_wsplit<<<16, 256, 0, g_s2>>>(W1l, W1r);
    k_gemm1_wmma<<<(N + 63) / 64, 256, GEMM1_SMEM, g_s2>>>(x, (float*)t1p, N);

    // join
    cudaEventRecord(g_evJoin, g_s2);
    cudaStreamWaitEvent(0, g_evJoin, 0);

    // layer-1 aggregate + sigmoid
    int tot1 = N * (HID / 4);
    k_finish<128, 64, true><<<(tot1 + 255) / 256, 256>>>((const float*)t1p, b1, (float*)hp, N);

    // layer 2
    constexpr int SMEM2 = (64 * 80 + 64 * 64) * 4;
    k_gemm_dual<64, 40, 64><<<(N + 63) / 64, 160, SMEM2>>>((const float*)hp, W2l, W2r, (float*)t2p, N);
    int tot2 = N * (NCLS / 4);
    k_finish<80, 40, false><<<(tot2 + 255) / 256, 256>>>((const float*)t2p, b2, out, N);
}

// round 9
// speedup vs baseline: 1.5082x; 1.0806x over previous
#include <cuda_runtime.h>
#include <cuda_bf16.h>
#include <mma.h>
#include <math.h>
#include <stdint.h>

using namespace nvcuda;

#define NFEAT 128
#define HID   64
#define NCLS  40
#define MAXN  100000
#define MAXE  600000
#define SCAN_CHUNK 4096
#define PADW 136                      // padded smem row for gemm1 (bf16 elems)
#define PADA2 72                      // gemm2 A row pad (K=64)
#define PADB2 88                      // gemm2 B row pad (N=80)

// ---------------- scratch ----------------
__device__ float g_t1[(size_t)MAXN * 128];   // [x@W1l | x@W1r]
__device__ float g_h [(size_t)MAXN * 64];    // hidden
__device__ float g_t2[(size_t)MAXN * 80];    // [h@W2l | h@W2r]
__device__ __nv_bfloat16 g_w1hi[128 * 128];
__device__ __nv_bfloat16 g_w1lo[128 * 128];
__device__ __nv_bfloat16 g_w2hi[64 * 80];
__device__ __nv_bfloat16 g_w2lo[64 * 80];
__device__ int   g_deg[MAXN];
__device__ int   g_cur[MAXN];
__device__ int   g_rowptr[MAXN + 1];
__device__ int   g_adj[MAXE];
__device__ int   g_bsum[32];
__device__ int   g_bflag[32];
__device__ int   g_is64;

// ---------------- side stream for capture fork (created once at load) -------
static cudaStream_t g_s2;
static cudaEvent_t  g_evFork, g_evJoin;
static struct _StreamInit {
    _StreamInit() {
        cudaStreamCreateWithFlags(&g_s2, cudaStreamNonBlocking);
        cudaEventCreateWithFlags(&g_evFork, cudaEventDisableTiming);
        cudaEventCreateWithFlags(&g_evJoin, cudaEventDisableTiming);
    }
} g_streamInit;

// ---------------- bf16 split helper ----------------
__device__ __forceinline__ void split4(const float4& v, uint32_t* hi2, uint32_t* lo2) {
    uint32_t h01, h23;
    asm("cvt.rn.bf16x2.f32 %0, %1, %2;" : "=r"(h01) : "f"(v.y), "f"(v.x));
    asm("cvt.rn.bf16x2.f32 %0, %1, %2;" : "=r"(h23) : "f"(v.w), "f"(v.z));
    float l0 = v.x - __uint_as_float(h01 << 16);
    float l1 = v.y - __uint_as_float(h01 & 0xffff0000u);
    float l2 = v.z - __uint_as_float(h23 << 16);
    float l3 = v.w - __uint_as_float(h23 & 0xffff0000u);
    asm("cvt.rn.bf16x2.f32 %0, %1, %2;" : "=r"(lo2[0]) : "f"(l1), "f"(l0));
    asm("cvt.rn.bf16x2.f32 %0, %1, %2;" : "=r"(lo2[1]) : "f"(l3), "f"(l2));
    hi2[0] = h01; hi2[1] = h23;
}

// ---------------- dtype detect ----------------
__global__ void k_detect(const void* __restrict__ ei, int E, int N) {
    __shared__ int bad;
    if (threadIdx.x == 0) bad = 0;
    __syncthreads();
    const long long* p = (const long long*)ei;
    int samples = (E < 512) ? E : 512;
    for (int i = threadIdx.x; i < samples; i += blockDim.x) {
        long long v = p[i];
        if (v < 0 || v >= (long long)N) atomicExch(&bad, 1);
    }
    __syncthreads();
    if (threadIdx.x == 0) g_is64 = bad ? 0 : 1;
}

__device__ __forceinline__ int load_idx(const void* ei, int pos) {
    if (g_is64) return (int)((const long long*)ei)[pos];
    return ((const int*)ei)[pos];
}

// ---------------- W splits ----------
__global__ void k_wsplit(const float* __restrict__ W1l, const float* __restrict__ W1r) {
    int p = blockIdx.x * blockDim.x + threadIdx.x;    // 4096 float4 slots
    int k = p >> 5, cq = p & 31;
    const float* src = (cq < 16) ? (W1l + k * 64 + cq * 4)
                                 : (W1r + k * 64 + (cq - 16) * 4);
    float4 v = *(const float4*)src;
    uint32_t hi2[2], lo2[2];
    split4(v, hi2, lo2);
    ((uint32_t*)(g_w1hi + k * 128 + cq * 4))[0] = hi2[0];
    ((uint32_t*)(g_w1hi + k * 128 + cq * 4))[1] = hi2[1];
    ((uint32_t*)(g_w1lo + k * 128 + cq * 4))[0] = lo2[0];
    ((uint32_t*)(g_w1lo + k * 128 + cq * 4))[1] = lo2[1];
}

__global__ void k_wsplit2(const float* __restrict__ W2l, const float* __restrict__ W2r) {
    int p = blockIdx.x * blockDim.x + threadIdx.x;    // 1280 float4 slots
    if (p >= 1280) return;
    int k = p / 20, cq = p % 20;
    const float* src = (cq < 10) ? (W2l + k * 40 + cq * 4)
                                 : (W2r + k * 40 + (cq - 10) * 4);
    float4 v = *(const float4*)src;
    uint32_t hi2[2], lo2[2];
    split4(v, hi2, lo2);
    ((uint32_t*)(g_w2hi + k * 80 + cq * 4))[0] = hi2[0];
    ((uint32_t*)(g_w2hi + k * 80 + cq * 4))[1] = hi2[1];
    ((uint32_t*)(g_w2lo + k * 80 + cq * 4))[0] = lo2[0];
    ((uint32_t*)(g_w2lo + k * 80 + cq * 4))[1] = lo2[1];
}

// g_deg is zero here (module load / re-zeroed by k_scan every call)
__global__ void k_hist(const void* __restrict__ ei, int E, int N) {
    int e = blockIdx.x * blockDim.x + threadIdx.x;
    if (e < E) {
        int dst = load_idx(ei, E + e);
        dst = min(max(dst, 0), N - 1);
        atomicAdd(&g_deg[dst], 1);
    }
}

// ---- single-pass scan with decoupled block-sum lookback ----
__global__ void k_scan(int n) {
    const int tid = threadIdx.x, lane = tid & 31, wid = tid >> 5;
    const int bid = blockIdx.x;
    __shared__ int wsum[32];
    __shared__ int s_off;
    int idx = bid * SCAN_CHUNK + tid * 4;
    int v0 = 0, v1 = 0, v2 = 0, v3 = 0;
    if (idx + 0 < n) { v0 = g_deg[idx + 0]; g_deg[idx + 0] = 0; }
    if (idx + 1 < n) { v1 = g_deg[idx + 1]; g_deg[idx + 1] = 0; }
    if (idx + 2 < n) { v2 = g_deg[idx + 2]; g_deg[idx + 2] = 0; }
    if (idx + 3 < n) { v3 = g_deg[idx + 3]; g_deg[idx + 3] = 0; }
    int s = v0 + v1 + v2 + v3;
    int sc = s;
    #pragma unroll
    for (int d = 1; d < 32; d <<= 1) {
        int t = __shfl_up_sync(0xffffffffu, sc, d);
        if (lane >= d) sc += t;
    }
    if (lane == 31) wsum[wid] = sc;
    __syncthreads();
    if (wid == 0) {
        int ws = wsum[lane];
        #pragma unroll
        for (int d = 1; d < 32; d <<= 1) {
            int t = __shfl_up_sync(0xffffffffu, ws, d);
            if (lane >= d) ws += t;
        }
        wsum[lane] = ws;
    }
    __syncthreads();
    int warp_excl = (wid == 0) ? 0 : wsum[wid - 1];
    int excl = warp_excl + (sc - s);

    if (tid == 1023) {
        g_bsum[bid] = warp_excl + sc;
        __threadfence();
        atomicExch(&g_bflag[bid], 1);
    }
    if (tid < 32) {
        int acc = 0;
        for (int j = lane; j < bid; j += 32) {
            while (atomicAdd(&g_bflag[j], 0) == 0) {}
            acc += atomicAdd(&g_bsum[j], 0);
        }
        #pragma unroll
        for (int d = 16; d > 0; d >>= 1)
            acc += __shfl_down_sync(0xffffffffu, acc, d);
        if (lane == 0) s_off = acc;
    }
    __syncthreads();
    int off = s_off + excl;
    int p0 = off + v0, p1 = p0 + v1, p2 = p1 + v2, p3 = p2 + v3;
    if (idx + 0 < n) g_rowptr[idx + 1] = p0;
    if (idx + 1 < n) g_rowptr[idx + 2] = p1;
    if (idx + 2 < n) g_rowptr[idx + 3] = p2;
    if (idx + 3 < n) g_rowptr[idx + 4] = p3;
    if (bid == 0 && tid == 0) g_rowptr[0] = 0;
}

// g_cur is zero here (module load / reset by final k_finish)
__global__ void k_fill(const void* __restrict__ ei, int E, int N) {
    if (blockIdx.x == 0 && threadIdx.x < 32) g_bflag[threadIdx.x] = 0;
    int e = blockIdx.x * blockDim.x + threadIdx.x;
    if (e < E) {
        int dst = load_idx(ei, E + e);
        int src = load_idx(ei, e);
        dst = min(max(dst, 0), N - 1);
        src = min(max(src, 0), N - 1);
        int pos = g_rowptr[dst] + atomicAdd(&g_cur[dst], 1);
        if (pos < E) g_adj[pos] = src;
    }
}

// ---------------- GEMM1 via WMMA bf16 split: T1 = X @ [W1l|W1r] ----------
#define GEMM1_SMEM ((2 * 128 + 2 * 64) * PADW * 2)

__global__ void __launch_bounds__(256, 2)
k_gemm1_wmma(const float* __restrict__ X, float* __restrict__ T, int n) {
    extern __shared__ char smraw[];
    __nv_bfloat16* Whi = (__nv_bfloat16*)smraw;          // [128][PADW]
    __nv_bfloat16* Wlo = Whi + 128 * PADW;
    __nv_bfloat16* Ahi = Wlo + 128 * PADW;               // [64][PADW]
    __nv_bfloat16* Alo = Ahi + 64 * PADW;
    const int tid = threadIdx.x, wid = tid >> 5;
    const int row0 = blockIdx.x * 64;

    #pragma unroll
    for (int it = 0; it < 8; it++) {
        int p = it * 256 + tid;
        int k = p >> 4, c = p & 15;
        *(uint4*)(Whi + k * PADW + c * 8) = ((const uint4*)g_w1hi)[p];
        *(uint4*)(Wlo + k * PADW + c * 8) = ((const uint4*)g_w1lo)[p];
    }
    #pragma unroll
    for (int it = 0; it < 8; it++) {
        int p = it * 256 + tid;
        int r = p >> 5, cq = p & 31;
        float4 v = make_float4(0.f, 0.f, 0.f, 0.f);
        if (row0 + r < n) v = ((const float4*)(X + (size_t)(row0 + r) * 128))[cq];
        uint32_t hi2[2], lo2[2];
        split4(v, hi2, lo2);
        uint32_t* ah = (uint32_t*)(Ahi + r * PADW + cq * 4);
        uint32_t* al = (uint32_t*)(Alo + r * PADW + cq * 4);
        ah[0] = hi2[0]; ah[1] = hi2[1];
        al[0] = lo2[0]; al[1] = lo2[1];
    }
    __syncthreads();

    const int m0 = (wid & 1) * 32;
    const int n0 = (wid >> 1) * 32;

    wmma::fragment<wmma::accumulator, 16, 16, 16, float> acc[2][2];
    #pragma unroll
    for (int r = 0; r < 2; r++)
        #pragma unroll
        for (int c = 0; c < 2; c++) wmma::fill_fragment(acc[r][c], 0.f);

    const __nv_bfloat16* Ap[3] = {Ahi, Ahi, Alo};
    const __nv_bfloat16* Bp[3] = {Whi, Wlo, Whi};

    #pragma unroll
    for (int pass = 0; pass < 3; pass++) {
        const __nv_bfloat16* A = Ap[pass];
        const __nv_bfloat16* B = Bp[pass];
        #pragma unroll
        for (int k = 0; k < 128; k += 16) {
            wmma::fragment<wmma::matrix_a, 16, 16, 16, __nv_bfloat16, wmma::row_major> a[2];
            wmma::load_matrix_sync(a[0], A + (m0 + 0)  * PADW + k, PADW);
            wmma::load_matrix_sync(a[1], A + (m0 + 16) * PADW + k, PADW);
            wmma::fragment<wmma::matrix_b, 16, 16, 16, __nv_bfloat16, wmma::row_major> b[2];
            wmma::load_matrix_sync(b[0], B + k * PADW + n0,      PADW);
            wmma::load_matrix_sync(b[1], B + k * PADW + n0 + 16, PADW);
            #pragma unroll
            for (int r = 0; r < 2; r++)
                #pragma unroll
                for (int c = 0; c < 2; c++)
                    wmma::mma_sync(acc[r][c], a[r], b[c], acc[r][c]);
        }
    }

    __syncthreads();
    float* stage = (float*)smraw;        // [64][128]
    #pragma unroll
    for (int r = 0; r < 2; r++)
        #pragma unroll
        for (int c = 0; c < 2; c++)
            wmma::store_matrix_sync(stage + (m0 + r * 16) * 128 + n0 + c * 16,
                                    acc[r][c], 128, wmma::mem_row_major);
    __syncthreads();
    #pragma unroll
    for (int it = 0; it < 8; it++) {
        int p = it * 256 + tid;
        int r = p >> 5, cq = p & 31;
        if (row0 + r < n)
            ((float4*)(T + (size_t)(row0 + r) * 128))[cq] = ((float4*)(stage + r * 128))[cq];
    }
}

// ---------------- GEMM2 via WMMA bf16 split: T2 = H @ [W2l|W2r] ----------------
// 128-row tile, 320 threads (10 warps = 2m x 5n; warp tile 64 rows x 16 cols).
#define GEMM2_SMEM ((2 * 64 * PADB2 + 2 * 128 * PADA2) * 2)

__global__ void __launch_bounds__(320, 2)
k_gemm2_wmma(const float* __restrict__ H, float* __restrict__ T, int n) {
    extern __shared__ char smraw[];
    __nv_bfloat16* Whi = (__nv_bfloat16*)smraw;           // [64][PADB2]
    __nv_bfloat16* Wlo = Whi + 64 * PADB2;
    __nv_bfloat16* Ahi = Wlo + 64 * PADB2;                // [128][PADA2]
    __nv_bfloat16* Alo = Ahi + 128 * PADA2;
    const int tid = threadIdx.x, wid = tid >> 5;
    const int row0 = blockIdx.x * 128;

    // W2 (64x80 bf16): 640 uint4 per matrix
    for (int p = tid; p < 640; p += 320) {
        int k = p / 10, c = p % 10;
        *(uint4*)(Whi + k * PADB2 + c * 8) = ((const uint4*)g_w2hi)[p];
        *(uint4*)(Wlo + k * PADB2 + c * 8) = ((const uint4*)g_w2lo)[p];
    }
    // H tile (128x64): 2048 float4
    for (int p = tid; p < 2048; p += 320) {
        int r = p >> 4, cq = p & 15;
        float4 v = make_float4(0.f, 0.f, 0.f, 0.f);
        if (row0 + r < n) v = ((const float4*)(H + (size_t)(row0 + r) * 64))[cq];
        uint32_t hi2[2], lo2[2];
        split4(v, hi2, lo2);
        uint32_t* ah = (uint32_t*)(Ahi + r * PADA2 + cq * 4);
        uint32_t* al = (uint32_t*)(Alo + r * PADA2 + cq * 4);
        ah[0] = hi2[0]; ah[1] = hi2[1];
        al[0] = lo2[0]; al[1] = lo2[1];
    }
    __syncthreads();

    const int n0 = (wid % 5) * 16;
    const int m0 = (wid / 5) * 64;

    wmma::fragment<wmma::accumulator, 16, 16, 16, float> acc[4];
    #pragma unroll
    for (int r = 0; r < 4; r++) wmma::fill_fragment(acc[r], 0.f);

    const __nv_bfloat16* Ap[3] = {Ahi, Ahi, Alo};
    const __nv_bfloat16* Bp[3] = {Whi, Wlo, Whi};

    #pragma unroll
    for (int pass = 0; pass < 3; pass++) {
        const __nv_bfloat16* A = Ap[pass];
        const __nv_bfloat16* B = Bp[pass];
        #pragma unroll
        for (int k = 0; k < 64; k += 16) {
            wmma::fragment<wmma::matrix_b, 16, 16, 16, __nv_bfloat16, wmma::row_major> b;
            wmma::load_matrix_sync(b, B + k * PADB2 + n0, PADB2);
            #pragma unroll
            for (int r = 0; r < 4; r++) {
                wmma::fragment<wmma::matrix_a, 16, 16, 16, __nv_bfloat16, wmma::row_major> a;
                wmma::load_matrix_sync(a, A + (m0 + r * 16) * PADA2 + k, PADA2);
                wmma::mma_sync(acc[r], a, b, acc[r]);
            }
        }
    }

    __syncthreads();
    float* stage = (float*)smraw;        // [128][80] = 40960B <= GEMM2_SMEM
    #pragma unroll
    for (int r = 0; r < 4; r++)
        wmma::store_matrix_sync(stage + (m0 + r * 16) * 80 + n0, acc[r], 80,
                                wmma::mem_row_major);
    __syncthreads();
    for (int p = tid; p < 2560; p += 320) {
        int r = p / 20, cq = p % 20;
        if (row0 + r < n)
            ((float4*)(T + (size_t)(row0 + r) * 80))[cq] = ((float4*)(stage + r * 80))[cq];
    }
}

// ---------------- aggregate + mean + residual + bias (+sigmoid) ----------------
template <int ROWLEN, int OUTC, bool SIG>
__global__ void k_finish(const float* __restrict__ T, const float* __restrict__ bias,
                         float* __restrict__ out, int n) {
    constexpr int Q = OUTC / 4;
    int gid = blockIdx.x * blockDim.x + threadIdx.x;
    int node = gid / Q;
    int q = gid - node * Q;
    if (node >= n) return;
    int s = g_rowptr[node], e = g_rowptr[node + 1];
    float4 acc = make_float4(0.f, 0.f, 0.f, 0.f);
    float4 acc2 = make_float4(0.f, 0.f, 0.f, 0.f);
    int p = s;
    for (; p + 1 < e; p += 2) {
        int j0 = g_adj[p], j1 = g_adj[p + 1];
        float4 v0 = *(const float4*)(T + (size_t)j0 * ROWLEN + q * 4);
        float4 v1 = *(const float4*)(T + (size_t)j1 * ROWLEN + q * 4);
        acc.x += v0.x; acc.y += v0.y; acc.z += v0.z; acc.w += v0.w;
        acc2.x += v1.x; acc2.y += v1.y; acc2.z += v1.z; acc2.w += v1.w;
    }
    if (p < e) {
        int j = g_adj[p];
        float4 v = *(const float4*)(T + (size_t)j * ROWLEN + q * 4);
        acc.x += v.x; acc.y += v.y; acc.z += v.z; acc.w += v.w;
    }
    acc.x += acc2.x; acc.y += acc2.y; acc.z += acc2.z; acc.w += acc2.w;
    float inv = 1.f / fmaxf((float)(e - s), 1.f);
    float4 r = *(const float4*)(T + (size_t)node * ROWLEN + OUTC + q * 4);
    float4 b = *(const float4*)(bias + q * 4);
    float4 o;
    o.x = fmaf(acc.x, inv, r.x + b.x);
    o.y = fmaf(acc.y, inv, r.y + b.y);
    o.z = fmaf(acc.z, inv, r.z + b.z);
    o.w = fmaf(acc.w, inv, r.w + b.w);
    if (SIG) {
        o.x = 1.f / (1.f + expf(-o.x));
        o.y = 1.f / (1.f + expf(-o.y));
        o.z = 1.f / (1.f + expf(-o.z));
        o.w = 1.f / (1.f + expf(-o.w));
    }
    *(float4*)(out + (size_t)node * OUTC + q * 4) = o;
    if (!SIG && q == 0) g_cur[node] = 0;   // reset for next call (final pass only)
}

// ---------------- launch ----------------
extern "C" void kernel_launch(void* const* d_in, const int* in_sizes, int n_in,
                              void* d_out, int out_size) {
    const float* x   = (const float*)d_in[0];
    const void*  ei  = d_in[1];
    const float* W1l = (const float*)d_in[2];
    const float* b1  = (const float*)d_in[3];
    const float* W1r = (const float*)d_in[4];
    const float* W2l = (const float*)d_in[5];
    const float* b2  = (const float*)d_in[6];
    const float* W2r = (const float*)d_in[7];
    float* out = (float*)d_out;

    const int N = in_sizes[0] / NFEAT;
    const int E = in_sizes[1] / 2;
    const int NB = (N + SCAN_CHUNK - 1) / SCAN_CHUNK;

    void *t1p, *hp, *t2p;
    cudaGetSymbolAddress(&t1p, g_t1);
    cudaGetSymbolAddress(&hp,  g_h);
    cudaGetSymbolAddress(&t2p, g_t2);

    cudaFuncSetAttribute(k_gemm1_wmma, cudaFuncAttributeMaxDynamicSharedMemorySize, GEMM1_SMEM);
    cudaFuncSetAttribute(k_gemm2_wmma, cudaFuncAttributeMaxDynamicSharedMemorySize, GEMM2_SMEM);

    // fork: side stream runs W splits + GEMM1 while main stream builds the graph
    cudaEventRecord(g_evFork, 0);
    cudaStreamWaitEvent(g_s2, g_evFork, 0);

    // main stream: graph build
    k_detect<<<1, 256>>>(ei, E, N);
    k_hist<<<(E + 255) / 256, 256>>>(ei, E, N);
    k_scan<<<NB, 1024>>>(N);
    k_fill<<<(E + 255) / 256, 256>>>(ei, E, N);

    // side stream: weight splits + layer-1 GEMM (independent of graph build)
    k_wsplit<<<16, 256, 0, g_s2>>>(W1l, W1r);
    k_wsplit2<<<5, 256, 0, g_s2>>>(W2l, W2r);
    k_gemm1_wmma<<<(N + 63) / 64, 256, GEMM1_SMEM, g_s2>>>(x, (float*)t1p, N);

    // join
    cudaEventRecord(g_evJoin, g_s2);
    cudaStreamWaitEvent(0, g_evJoin, 0);

    // layer-1 aggregate + sigmoid
    int tot1 = N * (HID / 4);
    k_finish<128, 64, true><<<(tot1 + 255) / 256, 256>>>((const float*)t1p, b1, (float*)hp, N);

    // layer 2: WMMA GEMM + final aggregate
    k_gemm2_wmma<<<(N + 127) / 128, 320, GEMM2_SMEM>>>((const float*)hp, (float*)t2p, N);
    int tot2 = N * (NCLS / 4);
    k_finish<80, 40, false><<<(tot2 + 255) / 256, 256>>>((const float*)t2p, b2, out, N);
}

// round 10
// speedup vs baseline: 1.5150x; 1.0045x over previous
#include <cuda_runtime.h>
#include <cuda_bf16.h>
#include <mma.h>
#include <math.h>
#include <stdint.h>

using namespace nvcuda;

#define NFEAT 128
#define HID   64
#define NCLS  40
#define MAXN  100000
#define MAXE  600000
#define SCAN_CHUNK 4096
#define PADW 136                      // padded smem row for gemm1 (bf16 elems)
#define PADA2 72                      // gemm2 A row pad (K=64)
#define PADB2 88                      // gemm2 B row pad (N=80)

// ---------------- scratch ----------------
__device__ float g_t1[(size_t)MAXN * 128];   // [x@W1l | x@W1r]
__device__ float g_h [(size_t)MAXN * 64];    // hidden
__device__ float g_t2[(size_t)MAXN * 80];    // [h@W2l | h@W2r]
__device__ __nv_bfloat16 g_w1hi[128 * 128];
__device__ __nv_bfloat16 g_w1lo[128 * 128];
__device__ __nv_bfloat16 g_w2hi[64 * 80];
__device__ __nv_bfloat16 g_w2lo[64 * 80];
__device__ int   g_deg[MAXN];
__device__ int   g_cur[MAXN];
__device__ int   g_rowptr[MAXN + 1];
__device__ int   g_adj[MAXE];
__device__ int   g_bsum[32];
__device__ int   g_bflag[32];

// ---------------- side stream + events (created once at load) -------
static cudaStream_t g_s2;
static cudaEvent_t  g_evFork, g_evFill, g_evG1, g_evT2;
static struct _StreamInit {
    _StreamInit() {
        cudaStreamCreateWithFlags(&g_s2, cudaStreamNonBlocking);
        cudaEventCreateWithFlags(&g_evFork, cudaEventDisableTiming);
        cudaEventCreateWithFlags(&g_evFill, cudaEventDisableTiming);
        cudaEventCreateWithFlags(&g_evG1,   cudaEventDisableTiming);
        cudaEventCreateWithFlags(&g_evT2,   cudaEventDisableTiming);
    }
} g_streamInit;

// ---------------- bf16 split helper ----------------
__device__ __forceinline__ void split4(const float4& v, uint32_t* hi2, uint32_t* lo2) {
    uint32_t h01, h23;
    asm("cvt.rn.bf16x2.f32 %0, %1, %2;" : "=r"(h01) : "f"(v.y), "f"(v.x));
    asm("cvt.rn.bf16x2.f32 %0, %1, %2;" : "=r"(h23) : "f"(v.w), "f"(v.z));
    float l0 = v.x - __uint_as_float(h01 << 16);
    float l1 = v.y - __uint_as_float(h01 & 0xffff0000u);
    float l2 = v.z - __uint_as_float(h23 << 16);
    float l3 = v.w - __uint_as_float(h23 & 0xffff0000u);
    asm("cvt.rn.bf16x2.f32 %0, %1, %2;" : "=r"(lo2[0]) : "f"(l1), "f"(l0));
    asm("cvt.rn.bf16x2.f32 %0, %1, %2;" : "=r"(lo2[1]) : "f"(l3), "f"(l2));
    hi2[0] = h01; hi2[1] = h23;
}

// ---------------- per-block inline dtype detect ----------------
// int32 data read as int64 has random hi words -> out of [0,N) almost surely.
__device__ __forceinline__ int detect_is64(const void* ei, int E, int N,
                                           int tid, int* s_flag) {
    if (tid < 32) {
        int samples = (E < 32) ? E : 32;
        bool bad = false;
        if (tid < samples) {
            long long v = ((const long long*)ei)[tid];
            bad = (v < 0 || v >= (long long)N);
        }
        unsigned m = __ballot_sync(0xffffffffu, bad);
        if (tid == 0) *s_flag = (m == 0u) ? 1 : 0;
    }
    __syncthreads();
    return *s_flag;
}

__device__ __forceinline__ int load_idx2(const void* ei, int pos, int is64) {
    if (is64) return (int)((const long long*)ei)[pos];
    return ((const int*)ei)[pos];
}

// ---------------- combined W split: W1 -> g_w1*, W2 -> g_w2* ----------
__global__ void k_wsplit_all(const float* __restrict__ W1l, const float* __restrict__ W1r,
                             const float* __restrict__ W2l, const float* __restrict__ W2r) {
    int p = blockIdx.x * blockDim.x + threadIdx.x;
    if (p < 4096) {                                    // W1: 4096 float4 slots
        int k = p >> 5, cq = p & 31;
        const float* src = (cq < 16) ? (W1l + k * 64 + cq * 4)
                                     : (W1r + k * 64 + (cq - 16) * 4);
        float4 v = *(const float4*)src;
        uint32_t hi2[2], lo2[2];
        split4(v, hi2, lo2);
        ((uint32_t*)(g_w1hi + k * 128 + cq * 4))[0] = hi2[0];
        ((uint32_t*)(g_w1hi + k * 128 + cq * 4))[1] = hi2[1];
        ((uint32_t*)(g_w1lo + k * 128 + cq * 4))[0] = lo2[0];
        ((uint32_t*)(g_w1lo + k * 128 + cq * 4))[1] = lo2[1];
    } else if (p < 4096 + 1280) {                      // W2: 1280 float4 slots
        int q = p - 4096;
        int k = q / 20, cq = q % 20;
        const float* src = (cq < 10) ? (W2l + k * 40 + cq * 4)
                                     : (W2r + k * 40 + (cq - 10) * 4);
        float4 v = *(const float4*)src;
        uint32_t hi2[2], lo2[2];
        split4(v, hi2, lo2);
        ((uint32_t*)(g_w2hi + k * 80 + cq * 4))[0] = hi2[0];
        ((uint32_t*)(g_w2hi + k * 80 + cq * 4))[1] = hi2[1];
        ((uint32_t*)(g_w2lo + k * 80 + cq * 4))[0] = lo2[0];
        ((uint32_t*)(g_w2lo + k * 80 + cq * 4))[1] = lo2[1];
    }
}

// g_deg is zero here (module load / re-zeroed by k_scan every call)
__global__ void k_hist(const void* __restrict__ ei, int E, int N) {
    __shared__ int s_flag;
    int is64 = detect_is64(ei, E, N, threadIdx.x, &s_flag);
    int half = (E + 1) >> 1;
    int e = blockIdx.x * blockDim.x + threadIdx.x;
    int d0 = -1, d1 = -1;
    if (e < half)        d0 = min(max(load_idx2(ei, E + e, is64), 0), N - 1);
    if (e + half < E)    d1 = min(max(load_idx2(ei, E + e + half, is64), 0), N - 1);
    if (d0 >= 0) atomicAdd(&g_deg[d0], 1);
    if (d1 >= 0) atomicAdd(&g_deg[d1], 1);
}

// ---- single-pass scan with decoupled block-sum lookback ----
__global__ void k_scan(int n) {
    const int tid = threadIdx.x, lane = tid & 31, wid = tid >> 5;
    const int bid = blockIdx.x;
    __shared__ int wsum[32];
    __shared__ int s_off;
    int idx = bid * SCAN_CHUNK + tid * 4;
    int v0 = 0, v1 = 0, v2 = 0, v3 = 0;
    if (idx + 0 < n) { v0 = g_deg[idx + 0]; g_deg[idx + 0] = 0; }
    if (idx + 1 < n) { v1 = g_deg[idx + 1]; g_deg[idx + 1] = 0; }
    if (idx + 2 < n) { v2 = g_deg[idx + 2]; g_deg[idx + 2] = 0; }
    if (idx + 3 < n) { v3 = g_deg[idx + 3]; g_deg[idx + 3] = 0; }
    int s = v0 + v1 + v2 + v3;
    int sc = s;
    #pragma unroll
    for (int d = 1; d < 32; d <<= 1) {
        int t = __shfl_up_sync(0xffffffffu, sc, d);
        if (lane >= d) sc += t;
    }
    if (lane == 31) wsum[wid] = sc;
    __syncthreads();
    if (wid == 0) {
        int ws = wsum[lane];
        #pragma unroll
        for (int d = 1; d < 32; d <<= 1) {
            int t = __shfl_up_sync(0xffffffffu, ws, d);
            if (lane >= d) ws += t;
        }
        wsum[lane] = ws;
    }
    __syncthreads();
    int warp_excl = (wid == 0) ? 0 : wsum[wid - 1];
    int excl = warp_excl + (sc - s);

    if (tid == 1023) {
        g_bsum[bid] = warp_excl + sc;
        __threadfence();
        atomicExch(&g_bflag[bid], 1);
    }
    if (tid < 32) {
        int acc = 0;
        for (int j = lane; j < bid; j += 32) {
            while (atomicAdd(&g_bflag[j], 0) == 0) {}
            acc += atomicAdd(&g_bsum[j], 0);
        }
        #pragma unroll
        for (int d = 16; d > 0; d >>= 1)
            acc += __shfl_down_sync(0xffffffffu, acc, d);
        if (lane == 0) s_off = acc;
    }
    __syncthreads();
    int off = s_off + excl;
    int p0 = off + v0, p1 = p0 + v1, p2 = p1 + v2, p3 = p2 + v3;
    if (idx + 0 < n) g_rowptr[idx + 1] = p0;
    if (idx + 1 < n) g_rowptr[idx + 2] = p1;
    if (idx + 2 < n) g_rowptr[idx + 3] = p2;
    if (idx + 3 < n) g_rowptr[idx + 4] = p3;
    if (bid == 0 && tid == 0) g_rowptr[0] = 0;
}

// g_cur is zero here (module load / reset by final k_finish)
__global__ void k_fill(const void* __restrict__ ei, int E, int N) {
    __shared__ int s_flag;
    int is64 = detect_is64(ei, E, N, threadIdx.x, &s_flag);
    if (blockIdx.x == 0 && threadIdx.x < 32) g_bflag[threadIdx.x] = 0;
    int half = (E + 1) >> 1;
    int e = blockIdx.x * blockDim.x + threadIdx.x;
    if (e < half) {
        int dst = min(max(load_idx2(ei, E + e, is64), 0), N - 1);
        int src = min(max(load_idx2(ei, e, is64), 0), N - 1);
        int pos = g_rowptr[dst] + atomicAdd(&g_cur[dst], 1);
        if (pos < E) g_adj[pos] = src;
    }
    if (e + half < E) {
        int dst = min(max(load_idx2(ei, E + e + half, is64), 0), N - 1);
        int src = min(max(load_idx2(ei, e + half, is64), 0), N - 1);
        int pos = g_rowptr[dst] + atomicAdd(&g_cur[dst], 1);
        if (pos < E) g_adj[pos] = src;
    }
}

// ---------------- GEMM1 via WMMA bf16 split: T1 = X @ [W1l|W1r] ----------
#define GEMM1_SMEM ((2 * 128 + 2 * 64) * PADW * 2)

__global__ void __launch_bounds__(256, 2)
k_gemm1_wmma(const float* __restrict__ X, float* __restrict__ T, int n) {
    extern __shared__ char smraw[];
    __nv_bfloat16* Whi = (__nv_bfloat16*)smraw;          // [128][PADW]
    __nv_bfloat16* Wlo = Whi + 128 * PADW;
    __nv_bfloat16* Ahi = Wlo + 128 * PADW;               // [64][PADW]
    __nv_bfloat16* Alo = Ahi + 64 * PADW;
    const int tid = threadIdx.x, wid = tid >> 5;
    const int row0 = blockIdx.x * 64;

    #pragma unroll
    for (int it = 0; it < 8; it++) {
        int p = it * 256 + tid;
        int k = p >> 4, c = p & 15;
        *(uint4*)(Whi + k * PADW + c * 8) = ((const uint4*)g_w1hi)[p];
        *(uint4*)(Wlo + k * PADW + c * 8) = ((const uint4*)g_w1lo)[p];
    }
    #pragma unroll
    for (int it = 0; it < 8; it++) {
        int p = it * 256 + tid;
        int r = p >> 5, cq = p & 31;
        float4 v = make_float4(0.f, 0.f, 0.f, 0.f);
        if (row0 + r < n) v = ((const float4*)(X + (size_t)(row0 + r) * 128))[cq];
        uint32_t hi2[2], lo2[2];
        split4(v, hi2, lo2);
        uint32_t* ah = (uint32_t*)(Ahi + r * PADW + cq * 4);
        uint32_t* al = (uint32_t*)(Alo + r * PADW + cq * 4);
        ah[0] = hi2[0]; ah[1] = hi2[1];
        al[0] = lo2[0]; al[1] = lo2[1];
    }
    __syncthreads();

    const int m0 = (wid & 1) * 32;
    const int n0 = (wid >> 1) * 32;

    wmma::fragment<wmma::accumulator, 16, 16, 16, float> acc[2][2];
    #pragma unroll
    for (int r = 0; r < 2; r++)
        #pragma unroll
        for (int c = 0; c < 2; c++) wmma::fill_fragment(acc[r][c], 0.f);

    const __nv_bfloat16* Ap[3] = {Ahi, Ahi, Alo};
    const __nv_bfloat16* Bp[3] = {Whi, Wlo, Whi};

    #pragma unroll
    for (int pass = 0; pass < 3; pass++) {
        const __nv_bfloat16* A = Ap[pass];
        const __nv_bfloat16* B = Bp[pass];
        #pragma unroll
        for (int k = 0; k < 128; k += 16) {
            wmma::fragment<wmma::matrix_a, 16, 16, 16, __nv_bfloat16, wmma::row_major> a[2];
            wmma::load_matrix_sync(a[0], A + (m0 + 0)  * PADW + k, PADW);
            wmma::load_matrix_sync(a[1], A + (m0 + 16) * PADW + k, PADW);
            wmma::fragment<wmma::matrix_b, 16, 16, 16, __nv_bfloat16, wmma::row_major> b[2];
            wmma::load_matrix_sync(b[0], B + k * PADW + n0,      PADW);
            wmma::load_matrix_sync(b[1], B + k * PADW + n0 + 16, PADW);
            #pragma unroll
            for (int r = 0; r < 2; r++)
                #pragma unroll
                for (int c = 0; c < 2; c++)
                    wmma::mma_sync(acc[r][c], a[r], b[c], acc[r][c]);
        }
    }

    __syncthreads();
    float* stage = (float*)smraw;        // [64][128]
    #pragma unroll
    for (int r = 0; r < 2; r++)
        #pragma unroll
        for (int c = 0; c < 2; c++)
            wmma::store_matrix_sync(stage + (m0 + r * 16) * 128 + n0 + c * 16,
                                    acc[r][c], 128, wmma::mem_row_major);
    __syncthreads();
    #pragma unroll
    for (int it = 0; it < 8; it++) {
        int p = it * 256 + tid;
        int r = p >> 5, cq = p & 31;
        if (row0 + r < n)
            ((float4*)(T + (size_t)(row0 + r) * 128))[cq] = ((float4*)(stage + r * 128))[cq];
    }
}

// ---------------- GEMM2 via WMMA bf16 split (row range): T2 = H @ [W2l|W2r] ----
#define GEMM2_SMEM ((2 * 64 * PADB2 + 2 * 128 * PADA2) * 2)

__global__ void __launch_bounds__(320, 2)
k_gemm2_wmma(const float* __restrict__ H, float* __restrict__ T, int base, int n) {
    extern __shared__ char smraw[];
    __nv_bfloat16* Whi = (__nv_bfloat16*)smraw;           // [64][PADB2]
    __nv_bfloat16* Wlo = Whi + 64 * PADB2;
    __nv_bfloat16* Ahi = Wlo + 64 * PADB2;                // [128][PADA2]
    __nv_bfloat16* Alo = Ahi + 128 * PADA2;
    const int tid = threadIdx.x, wid = tid >> 5;
    const int row0 = base + blockIdx.x * 128;

    for (int p = tid; p < 640; p += 320) {
        int k = p / 10, c = p % 10;
        *(uint4*)(Whi + k * PADB2 + c * 8) = ((const uint4*)g_w2hi)[p];
        *(uint4*)(Wlo + k * PADB2 + c * 8) = ((const uint4*)g_w2lo)[p];
    }
    for (int p = tid; p < 2048; p += 320) {
        int r = p >> 4, cq = p & 15;
        float4 v = make_float4(0.f, 0.f, 0.f, 0.f);
        if (row0 + r < n) v = ((const float4*)(H + (size_t)(row0 + r) * 64))[cq];
        uint32_t hi2[2], lo2[2];
        split4(v, hi2, lo2);
        uint32_t* ah = (uint32_t*)(Ahi + r * PADA2 + cq * 4);
        uint32_t* al = (uint32_t*)(Alo + r * PADA2 + cq * 4);
        ah[0] = hi2[0]; ah[1] = hi2[1];
        al[0] = lo2[0]; al[1] = lo2[1];
    }
    __syncthreads();

    const int n0 = (wid % 5) * 16;
    const int m0 = (wid / 5) * 64;

    wmma::fragment<wmma::accumulator, 16, 16, 16, float> acc[4];
    #pragma unroll
    for (int r = 0; r < 4; r++) wmma::fill_fragment(acc[r], 0.f);

    const __nv_bfloat16* Ap[3] = {Ahi, Ahi, Alo};
    const __nv_bfloat16* Bp[3] = {Whi, Wlo, Whi};

    #pragma unroll
    for (int pass = 0; pass < 3; pass++) {
        const __nv_bfloat16* A = Ap[pass];
        const __nv_bfloat16* B = Bp[pass];
        #pragma unroll
        for (int k = 0; k < 64; k += 16) {
            wmma::fragment<wmma::matrix_b, 16, 16, 16, __nv_bfloat16, wmma::row_major> b;
            wmma::load_matrix_sync(b, B + k * PADB2 + n0, PADB2);
            #pragma unroll
            for (int r = 0; r < 4; r++) {
                wmma::fragment<wmma::matrix_a, 16, 16, 16, __nv_bfloat16, wmma::row_major> a;
                wmma::load_matrix_sync(a, A + (m0 + r * 16) * PADA2 + k, PADA2);
                wmma::mma_sync(acc[r], a, b, acc[r]);
            }
        }
    }

    __syncthreads();
    float* stage = (float*)smraw;        // [128][80]
    #pragma unroll
    for (int r = 0; r < 4; r++)
        wmma::store_matrix_sync(stage + (m0 + r * 16) * 80 + n0, acc[r], 80,
                                wmma::mem_row_major);
    __syncthreads();
    for (int p = tid; p < 2560; p += 320) {
        int r = p / 20, cq = p % 20;
        if (row0 + r < n)
            ((float4*)(T + (size_t)(row0 + r) * 80))[cq] = ((float4*)(stage + r * 80))[cq];
    }
}

// -------- aggregate + mean + residual + bias (+sigmoid), node range --------
template <int ROWLEN, int OUTC, bool SIG>
__global__ void k_finish(const float* __restrict__ T, const float* __restrict__ bias,
                         float* __restrict__ out, int base, int n) {
    constexpr int Q = OUTC / 4;
    int gid = blockIdx.x * blockDim.x + threadIdx.x;
    int node = base + gid / Q;
    int q = gid - (gid / Q) * Q;
    if (node >= n) return;
    int s = g_rowptr[node], e = g_rowptr[node + 1];
    float4 acc = make_float4(0.f, 0.f, 0.f, 0.f);
    float4 acc2 = make_float4(0.f, 0.f, 0.f, 0.f);
    int p = s;
    for (; p + 1 < e; p += 2) {
        int j0 = g_adj[p], j1 = g_adj[p + 1];
        float4 v0 = *(const float4*)(T + (size_t)j0 * ROWLEN + q * 4);
        float4 v1 = *(const float4*)(T + (size_t)j1 * ROWLEN + q * 4);
        acc.x += v0.x; acc.y += v0.y; acc.z += v0.z; acc.w += v0.w;
        acc2.x += v1.x; acc2.y += v1.y; acc2.z += v1.z; acc2.w += v1.w;
    }
    if (p < e) {
        int j = g_adj[p];
        float4 v = *(const float4*)(T + (size_t)j * ROWLEN + q * 4);
        acc.x += v.x; acc.y += v.y; acc.z += v.z; acc.w += v.w;
    }
    acc.x += acc2.x; acc.y += acc2.y; acc.z += acc2.z; acc.w += acc2.w;
    float inv = 1.f / fmaxf((float)(e - s), 1.f);
    float4 r = *(const float4*)(T + (size_t)node * ROWLEN + OUTC + q * 4);
    float4 b = *(const float4*)(bias + q * 4);
    float4 o;
    o.x = fmaf(acc.x, inv, r.x + b.x);
    o.y = fmaf(acc.y, inv, r.y + b.y);
    o.z = fmaf(acc.z, inv, r.z + b.z);
    o.w = fmaf(acc.w, inv, r.w + b.w);
    if (SIG) {
        o.x = 1.f / (1.f + expf(-o.x));
        o.y = 1.f / (1.f + expf(-o.y));
        o.z = 1.f / (1.f + expf(-o.z));
        o.w = 1.f / (1.f + expf(-o.w));
    }
    *(float4*)(out + (size_t)node * OUTC + q * 4) = o;
    if (!SIG && q == 0) g_cur[node] = 0;   // reset for next call (final pass only)
}

// ---------------- launch ----------------
extern "C" void kernel_launch(void* const* d_in, const int* in_sizes, int n_in,
                              void* d_out, int out_size) {
    const float* x   = (const float*)d_in[0];
    const void*  ei  = d_in[1];
    const float* W1l = (const float*)d_in[2];
    const float* b1  = (const float*)d_in[3];
    const float* W1r = (const float*)d_in[4];
    const float* W2l = (const float*)d_in[5];
    const float* b2  = (const float*)d_in[6];
    const float* W2r = (const float*)d_in[7];
    float* out = (float*)d_out;

    const int N = in_sizes[0] / NFEAT;
    const int E = in_sizes[1] / 2;
    const int NB = (N + SCAN_CHUNK - 1) / SCAN_CHUNK;
    const int EH = ((E + 1) / 2 + 255) / 256;            // grid for 2-edge kernels
    int NH = ((N / 2 + 127) / 128) * 128;                // half split, 128-aligned
    if (NH > N) NH = N;

    void *t1p, *hp, *t2p;
    cudaGetSymbolAddress(&t1p, g_t1);
    cudaGetSymbolAddress(&hp,  g_h);
    cudaGetSymbolAddress(&t2p, g_t2);

    cudaFuncSetAttribute(k_gemm1_wmma, cudaFuncAttributeMaxDynamicSharedMemorySize, GEMM1_SMEM);
    cudaFuncSetAttribute(k_gemm2_wmma, cudaFuncAttributeMaxDynamicSharedMemorySize, GEMM2_SMEM);

    // fork
    cudaEventRecord(g_evFork, 0);
    cudaStreamWaitEvent(g_s2, g_evFork, 0);

    // main stream: graph build
    k_hist<<<EH, 256>>>(ei, E, N);
    k_scan<<<NB, 1024>>>(N);
    k_fill<<<EH, 256>>>(ei, E, N);
    cudaEventRecord(g_evFill, 0);

    // side stream: weight splits + layer-1 GEMM
    k_wsplit_all<<<21, 256, 0, g_s2>>>(W1l, W1r, W2l, W2r);
    k_gemm1_wmma<<<(N + 63) / 64, 256, GEMM1_SMEM, g_s2>>>(x, (float*)t1p, N);
    cudaEventRecord(g_evG1, g_s2);

    // side stream continues with upper half of the tail (needs fill too)
    cudaStreamWaitEvent(g_s2, g_evFill, 0);
    if (N > NH) {
        int tot1b = (N - NH) * (HID / 4);
        k_finish<128, 64, true><<<(tot1b + 255) / 256, 256, 0, g_s2>>>(
            (const float*)t1p, b1, (float*)hp, NH, N);
        k_gemm2_wmma<<<(N - NH + 127) / 128, 320, GEMM2_SMEM, g_s2>>>(
            (const float*)hp, (float*)t2p, NH, N);
    }
    cudaEventRecord(g_evT2, g_s2);

    // main stream: lower half of the tail (needs gemm1 from side)
    cudaStreamWaitEvent(0, g_evG1, 0);
    int tot1a = NH * (HID / 4);
    k_finish<128, 64, true><<<(tot1a + 255) / 256, 256>>>(
        (const float*)t1p, b1, (float*)hp, 0, N);
    k_gemm2_wmma<<<NH / 128, 320, GEMM2_SMEM>>>((const float*)hp, (float*)t2p, 0, N);

    // join + final aggregate over all nodes
    cudaStreamWaitEvent(0, g_evT2, 0);
    int tot2 = N * (NCLS / 4);
    k_finish<80, 40, false><<<(tot2 + 255) / 256, 256>>>(
        (const float*)t2p, b2, out, 0, N);
}